// round 14
// baseline (speedup 1.0000x reference)
#include <cuda_runtime.h>
#include <cuda_fp16.h>
#include <cstdint>

#define BB   4
#define SS   2048
#define DD   1024
#define DQKC 128
#define DVC  256
#define MM   (BB * SS)   // 8192
#define NPROJ 768

// ---------------------------------------------------------------------------
// Device scratch (all fp16 operands)
// ---------------------------------------------------------------------------
__device__ __align__(256) __half g_Xh[MM * DD];
__device__ __align__(256) __half g_Wt[NPROJ * DD];      // [n][k]
__device__ __align__(256) __half g_Wpt[DD * DVC];       // [n][k]
__device__ __align__(256) __half g_Qh[MM * DQKC];
__device__ __align__(256) __half g_Kh[MM * DQKC];
__device__ __align__(256) __half g_Vt[BB * DVC * SS];   // [b][n][s]
__device__ __align__(256) __half g_Gh[MM * DVC];
__device__ __align__(256) __half g_Ph[MM * DVC];        // (AV*G)
__device__ __align__(256) float g_Q2[MM];
__device__ __align__(256) float g_K2[MM];

// ---------------------------------------------------------------------------
// PTX helpers
// ---------------------------------------------------------------------------
__device__ __forceinline__ uint32_t smem_u32(const void* p) {
    uint32_t a;
    asm("{ .reg .u64 t; cvta.to.shared.u64 t, %1; cvt.u32.u64 %0, t; }"
        : "=r"(a) : "l"(p));
    return a;
}

#define LDSM4(r, addr) \
    asm volatile("ldmatrix.sync.aligned.m8n8.x4.shared.b16 {%0,%1,%2,%3}, [%4];" \
        : "=r"((r)[0]), "=r"((r)[1]), "=r"((r)[2]), "=r"((r)[3]) : "r"(addr))

#define MMA16816(c, a, b0, b1) \
    asm volatile("mma.sync.aligned.m16n8k16.row.col.f32.f16.f16.f32 " \
        "{%0,%1,%2,%3}, {%4,%5,%6,%7}, {%8,%9}, {%0,%1,%2,%3};" \
        : "+f"((c)[0]), "+f"((c)[1]), "+f"((c)[2]), "+f"((c)[3]) \
        : "r"((a)[0]), "r"((a)[1]), "r"((a)[2]), "r"((a)[3]), "r"(b0), "r"(b1))

#define CPA16(s, g) \
    asm volatile("cp.async.ca.shared.global [%0], [%1], 16;" :: "r"(s), "l"(g) : "memory")
#define CP_COMMIT() asm volatile("cp.async.commit_group;" ::: "memory")
#define CP_WAIT0()  asm volatile("cp.async.wait_group 0;" ::: "memory")
#define CP_WAIT1()  asm volatile("cp.async.wait_group 1;" ::: "memory")
#define CP_WAIT4()  asm volatile("cp.async.wait_group 4;" ::: "memory")
#define CP_WAIT5()  asm volatile("cp.async.wait_group 5;" ::: "memory")

__device__ __forceinline__ uint32_t pack2h(float a, float b) {
    __half2 hp(__float2half_rn(a), __float2half_rn(b));
    return *reinterpret_cast<uint32_t*>(&hp);
}

// ---------------------------------------------------------------------------
// Prep: one kernel. Blocks [0, XB) convert X; rest convert W^T.
// ---------------------------------------------------------------------------
#define XB (MM * DD / 1024)
#define WB ((NPROJ * DD + DD * DVC) / 256)

__global__ __launch_bounds__(256) void prep_kernel(
    const float* __restrict__ X,
    const float* __restrict__ Wq, const float* __restrict__ Wk,
    const float* __restrict__ Wv, const float* __restrict__ Wg,
    const float* __restrict__ Wp)
{
    if (blockIdx.x < XB) {
        int i = (blockIdx.x * 256 + threadIdx.x) * 4;
        float4 v = *(const float4*)&X[i];
        *(uint2*)&g_Xh[i] = make_uint2(pack2h(v.x, v.y), pack2h(v.z, v.w));
    } else {
        int idx = (blockIdx.x - XB) * 256 + threadIdx.x;
        if (idx < NPROJ * DD) {
            int n = idx >> 10, k = idx & 1023;
            const float* W; int col; int ncols;
            if (n < 128)      { W = Wq; col = n;       ncols = 128; }
            else if (n < 256) { W = Wk; col = n - 128; ncols = 128; }
            else if (n < 512) { W = Wv; col = n - 256; ncols = 256; }
            else              { W = Wg; col = n - 512; ncols = 256; }
            g_Wt[idx] = __float2half_rn(W[k * ncols + col]);
        } else {
            int j = idx - NPROJ * DD;
            int n = j >> 8, k = j & 255;
            g_Wpt[j] = __float2half_rn(Wp[k * DD + n]);
        }
    }
}

// ---------------------------------------------------------------------------
// GEMM machinery (proj): single fp16, BK=64, pitch-144 tiles, 2 stages.
// ---------------------------------------------------------------------------
#define TILE_BYTES   18432
#define STAGE_BYTES  (2 * TILE_BYTES)
#define GEMM_SMEM_BYTES (2 * STAGE_BYTES)

__device__ __forceinline__ void stage_copy(
    uint32_t sstage,
    const __half* __restrict__ A, int lda,
    const __half* __restrict__ B, int ldb, int k0, int tid)
{
    #pragma unroll
    for (int i = 0; i < 4; i++) {
        int idx = tid + i * 256;
        int row = idx >> 3;
        int seg = idx & 7;
        uint32_t so = row * 144 + seg * 16;
        CPA16(sstage +              so, A + (size_t)row * lda + k0 + seg * 8);
        CPA16(sstage + TILE_BYTES + so, B + (size_t)row * ldb + k0 + seg * 8);
    }
}

__device__ __forceinline__ void compute_stage(
    uint32_t sstage, uint32_t a_off, uint32_t b_off, float acc[4][4][4])
{
    #pragma unroll
    for (int ks = 0; ks < 4; ks++) {
        uint32_t ah[4][4], bh[2][4];
        #pragma unroll
        for (int mf = 0; mf < 4; mf++)
            LDSM4(ah[mf], sstage + a_off + mf * 2304 + ks * 32);
        #pragma unroll
        for (int np = 0; np < 2; np++)
            LDSM4(bh[np], sstage + TILE_BYTES + b_off + np * 2304 + ks * 32);
        #pragma unroll
        for (int mf = 0; mf < 4; mf++) {
            #pragma unroll
            for (int nf = 0; nf < 4; nf++) {
                MMA16816(acc[mf][nf], ah[mf],
                         bh[nf >> 1][(nf & 1) * 2], bh[nf >> 1][(nf & 1) * 2 + 1]);
            }
        }
    }
}

// ---------------------------------------------------------------------------
// proj_gemm: grid (64, 6), 256 threads, 2 CTAs/SM. Fused epilogues.
// ---------------------------------------------------------------------------
__global__ __launch_bounds__(256, 2) void proj_gemm(
    const float* __restrict__ bq, const float* __restrict__ bk,
    const float* __restrict__ bv, const float* __restrict__ bg)
{
    extern __shared__ char smraw[];
    __shared__ float sq2[128];
    uint32_t sbase = smem_u32(smraw);
    const int tid = threadIdx.x;
    const int m0 = blockIdx.x * 128;
    const int slab = blockIdx.y;
    const int nbase = slab * 128;

    if (tid < 128) sq2[tid] = 0.0f;

    const __half* A = g_Xh + (size_t)m0 * DD;
    const __half* B = g_Wt + (size_t)nbase * DD;

    const int warp = tid >> 5, lane = tid & 31;
    const int lr = lane & 7, gq = lane >> 3;
    const int wm = (warp & 1) * 64, wn = (warp >> 1) * 32;
    const uint32_t a_off = (wm + lr + (gq & 1) * 8) * 144 + (gq >> 1) * 16;
    const uint32_t b_off = (wn + lr + (gq >> 1) * 8) * 144 + (gq & 1) * 16;

    float acc[4][4][4] = {};

    stage_copy(sbase, A, DD, B, DD, 0, tid);
    CP_COMMIT();
    for (int kb = 0; kb < 16; kb++) {
        if (kb + 1 < 16) {
            stage_copy(sbase + ((kb + 1) & 1) * STAGE_BYTES,
                       A, DD, B, DD, (kb + 1) * 64, tid);
            CP_COMMIT();
            CP_WAIT1();
        } else {
            CP_WAIT0();
        }
        __syncthreads();
        compute_stage(sbase + (kb & 1) * STAGE_BYTES, a_off, b_off, acc);
        __syncthreads();
    }

    const int mrow = lane >> 2, ncol = (lane & 3) * 2;

    if (slab < 2) {
        const float* bias = (slab == 0) ? bq : bk;
        __half* dst = (slab == 0) ? g_Qh : g_Kh;
        float part[4][2] = {};
        #pragma unroll
        for (int mf = 0; mf < 4; mf++) {
            int lm = wm + mf * 16 + mrow;
            #pragma unroll
            for (int nf = 0; nf < 4; nf++) {
                int n = wn + nf * 8 + ncol;
                float b0 = bias[n], b1 = bias[n + 1];
                __half h00 = __float2half_rn(acc[mf][nf][0] + b0);
                __half h01 = __float2half_rn(acc[mf][nf][1] + b1);
                __half h10 = __float2half_rn(acc[mf][nf][2] + b0);
                __half h11 = __float2half_rn(acc[mf][nf][3] + b1);
                __half2 p0(h00, h01), p1(h10, h11);
                *(uint32_t*)&dst[(size_t)(m0 + lm) * DQKC + n] =
                    *reinterpret_cast<uint32_t*>(&p0);
                *(uint32_t*)&dst[(size_t)(m0 + lm + 8) * DQKC + n] =
                    *reinterpret_cast<uint32_t*>(&p1);
                float f00 = __half2float(h00), f01 = __half2float(h01);
                float f10 = __half2float(h10), f11 = __half2float(h11);
                part[mf][0] += f00 * f00 + f01 * f01;
                part[mf][1] += f10 * f10 + f11 * f11;
            }
        }
        #pragma unroll
        for (int mf = 0; mf < 4; mf++) {
            float s0 = part[mf][0], s1 = part[mf][1];
            s0 += __shfl_xor_sync(0xffffffffu, s0, 1);
            s0 += __shfl_xor_sync(0xffffffffu, s0, 2);
            s1 += __shfl_xor_sync(0xffffffffu, s1, 1);
            s1 += __shfl_xor_sync(0xffffffffu, s1, 2);
            if ((lane & 3) == 0) {
                int lm = wm + mf * 16 + mrow;
                atomicAdd(&sq2[lm], s0);
                atomicAdd(&sq2[lm + 8], s1);
            }
        }
        __syncthreads();
        if (tid < 128) {
            if (slab == 0) g_Q2[m0 + tid] = sq2[tid];
            else           g_K2[m0 + tid] = sq2[tid];
        }
    } else if (slab < 4) {
        __half* Vs = (__half*)smraw;
        const int VSP = 130;
        #pragma unroll
        for (int mf = 0; mf < 4; mf++) {
            int lm = wm + mf * 16 + mrow;
            #pragma unroll
            for (int nf = 0; nf < 4; nf++) {
                int n = wn + nf * 8 + ncol;
                float b0 = bv[((slab == 3) ? 128 : 0) + n];
                float b1 = bv[((slab == 3) ? 128 : 0) + n + 1];
                *(uint32_t*)&Vs[lm * VSP + n] =
                    pack2h(acc[mf][nf][0] + b0, acc[mf][nf][1] + b1);
                *(uint32_t*)&Vs[(lm + 8) * VSP + n] =
                    pack2h(acc[mf][nf][2] + b0, acc[mf][nf][3] + b1);
            }
        }
        __syncthreads();
        const int batch = m0 >> 11;
        const int mloc  = m0 & 2047;
        const int nbo   = (slab == 3) ? 128 : 0;
        #pragma unroll
        for (int i = 0; i < 8; i++) {
            int idx = tid + i * 256;
            int n = idx >> 4;
            int mseg = idx & 15;
            __half tmp[8];
            #pragma unroll
            for (int j = 0; j < 8; j++)
                tmp[j] = Vs[(mseg * 8 + j) * VSP + n];
            *(uint4*)&g_Vt[((size_t)batch * DVC + nbo + n) * SS + mloc + mseg * 8] =
                *(uint4*)tmp;
        }
    } else {
        const int nbo = (slab == 5) ? 128 : 0;
        #pragma unroll
        for (int mf = 0; mf < 4; mf++) {
            int m = m0 + wm + mf * 16 + mrow;
            #pragma unroll
            for (int nf = 0; nf < 4; nf++) {
                int n = wn + nf * 8 + ncol;
                float b0 = bg[nbo + n], b1 = bg[nbo + n + 1];
                *(uint32_t*)&g_Gh[(size_t)m * DVC + nbo + n] =
                    pack2h(acc[mf][nf][0] + b0, acc[mf][nf][1] + b1);
                *(uint32_t*)&g_Gh[(size_t)(m + 8) * DVC + nbo + n] =
                    pack2h(acc[mf][nf][2] + b0, acc[mf][nf][3] + b1);
            }
        }
    }
}

// ---------------------------------------------------------------------------
// attn: register-resident w (R13).
// ---------------------------------------------------------------------------
#define QPITCH 272
#define KPITCH 272
#define VPITCH 144

#define KBUF_BYTES 17408
#define VBUF_BYTES 36864

#define OFF_QH  0
#define OFF_KH  17408
#define OFF_VH  69632
#define OFF_K2  180224
#define ATT_SMEM_BYTES 180992

#define WSCALE 1024.0f

__device__ __forceinline__ void attn_load_k(uint32_t sKh, int krow0c, int tid)
{
    #pragma unroll
    for (int i = 0; i < 4; i++) {
        int idx = tid + i * 256;
        int row = idx >> 4, seg = idx & 15;
        CPA16(sKh + row * KPITCH + seg * 16,
              g_Kh + (size_t)(krow0c + row) * DQKC + seg * 8);
    }
}

__device__ __forceinline__ void attn_load_v(uint32_t sVh, int b, int kb, int tid)
{
    #pragma unroll
    for (int i = 0; i < 8; i++) {
        int idx = tid + i * 256;
        int n = idx >> 3, seg = idx & 7;
        CPA16(sVh + n * VPITCH + seg * 16,
              g_Vt + ((size_t)b * DVC + n) * (size_t)SS + kb * 64 + seg * 8);
    }
}

__global__ __launch_bounds__(256) void attn_kernel()
{
    extern __shared__ char smc[];
    const uint32_t sb = smem_u32(smc);

    const int tid  = threadIdx.x;
    const int warp = tid >> 5, lane = tid & 31;
    const int lr = lane & 7, gq = lane >> 3;
    const int mrow = lane >> 2, ncol = (lane & 3) * 2;
    const int rg = warp & 3;
    const int ch = warp >> 2;

    const int b  = blockIdx.x >> 5;
    const int qt = blockIdx.x & 31;
    const int qrow0 = b * SS + qt * 64;
    const int krow0 = b * SS;

    #pragma unroll
    for (int i = 0; i < 4; i++) {
        int idx = tid + i * 256;
        int row = idx >> 4, seg = idx & 15;
        CPA16(sb + OFF_QH + row * QPITCH + seg * 16,
              g_Qh + (size_t)(qrow0 + row) * DQKC + seg * 8);
    }
    attn_load_k(sb + OFF_KH, krow0, tid);
    if (tid < 16) CPA16(sb + OFF_K2 + tid * 16, g_K2 + krow0 + tid * 4);
    CP_COMMIT();
    attn_load_v(sb + OFF_VH, b, 0, tid);
    CP_COMMIT();
    attn_load_k(sb + OFF_KH + KBUF_BYTES, krow0 + 64, tid);
    if (tid < 16) CPA16(sb + OFF_K2 + 256 + tid * 16, g_K2 + krow0 + 64 + tid * 4);
    CP_COMMIT();
    attn_load_v(sb + OFF_VH + VBUF_BYTES, b, 1, tid);
    CP_COMMIT();

    const int r0 = rg * 16 + mrow;
    const float q20 = g_Q2[qrow0 + r0];
    const float q21 = g_Q2[qrow0 + r0 + 8];
    float rs0 = 0.0f, rs1 = 0.0f;

    const uint32_t aQbase = sb + OFF_QH +
        (rg * 16 + lr + (gq & 1) * 8) * QPITCH + (gq >> 1) * 16;
    const uint32_t bK = (lr + (gq >> 1) * 8) * KPITCH + (gq & 1) * 16;
    const uint32_t bV = (ch * 128 + lr + (gq >> 1) * 8) * VPITCH + (gq & 1) * 16;

    float acc[16][4] = {};

    for (int kc = 0; kc < 32; kc++) {
        __syncthreads();

        if (kc + 2 < 32) {
            int j = (kc + 2) % 3;
            attn_load_k(sb + OFF_KH + j * KBUF_BYTES, krow0 + (kc + 2) * 64, tid);
            if (tid < 16) CPA16(sb + OFF_K2 + j * 256 + tid * 16,
                                g_K2 + krow0 + (kc + 2) * 64 + tid * 4);
        }
        CP_COMMIT();
        if (kc + 2 < 32) {
            int j = (kc + 2) % 3;
            attn_load_v(sb + OFF_VH + j * VBUF_BYTES, b, kc + 2, tid);
        }
        CP_COMMIT();

        CP_WAIT5();

        const uint32_t sKH = sb + OFF_KH + (kc % 3) * KBUF_BYTES + bK;
        float s[8][4];
        #pragma unroll
        for (int nt = 0; nt < 8; nt++)
            #pragma unroll
            for (int k = 0; k < 4; k++) s[nt][k] = 0.0f;
        #pragma unroll
        for (int ks = 0; ks < 8; ks++) {
            uint32_t ah[4], bh[4][4];
            LDSM4(ah, aQbase + ks * 32);
            #pragma unroll
            for (int np = 0; np < 4; np++)
                LDSM4(bh[np], sKH + np * 16 * KPITCH + ks * 32);
            #pragma unroll
            for (int nt = 0; nt < 8; nt++)
                MMA16816(s[nt], ah, bh[nt >> 1][(nt & 1) * 2],
                         bh[nt >> 1][(nt & 1) * 2 + 1]);
        }

        const float* k2c = (const float*)(smc + OFF_K2 + (kc % 3) * 256);
        uint32_t wf[4][4];
        #pragma unroll
        for (int nt = 0; nt < 8; nt++) {
            float k20 = k2c[nt * 8 + ncol], k21 = k2c[nt * 8 + ncol + 1];
            float d00 = fmaxf(fmaf(-2.0f, s[nt][0], q20 + k20), 1e-6f);
            float d01 = fmaxf(fmaf(-2.0f, s[nt][1], q20 + k21), 1e-6f);
            float d10 = fmaxf(fmaf(-2.0f, s[nt][2], q21 + k20), 1e-6f);
            float d11 = fmaxf(fmaf(-2.0f, s[nt][3], q21 + k21), 1e-6f);
            float w00 = __fdividef(WSCALE, d00);
            float w01 = __fdividef(WSCALE, d01);
            float w10 = __fdividef(WSCALE, d10);
            float w11 = __fdividef(WSCALE, d11);
            rs0 += w00 + w01;
            rs1 += w10 + w11;
            int ks = nt >> 1, ix = (nt & 1) * 2;
            wf[ks][ix]     = pack2h(w00, w01);
            wf[ks][ix + 1] = pack2h(w10, w11);
        }

        CP_WAIT4();

        const uint32_t sVH = sb + OFF_VH + (kc % 3) * VBUF_BYTES + bV;
        #pragma unroll
        for (int ks = 0; ks < 4; ks++) {
            uint32_t bvh[8][4];
            #pragma unroll
            for (int nn = 0; nn < 8; nn++)
                LDSM4(bvh[nn], sVH + nn * 16 * VPITCH + ks * 32);
            #pragma unroll
            for (int nf = 0; nf < 16; nf++)
                MMA16816(acc[nf], wf[ks], bvh[nf >> 1][(nf & 1) * 2],
                         bvh[nf >> 1][(nf & 1) * 2 + 1]);
        }
    }

    rs0 += __shfl_xor_sync(0xffffffffu, rs0, 1);
    rs0 += __shfl_xor_sync(0xffffffffu, rs0, 2);
    rs1 += __shfl_xor_sync(0xffffffffu, rs1, 1);
    rs1 += __shfl_xor_sync(0xffffffffu, rs1, 2);
    const float inv0 = 1.0f / rs0;
    const float inv1 = 1.0f / rs1;
    const size_t gm0 = (size_t)(qrow0 + r0) * DVC;
    const size_t gm1 = gm0 + 8 * DVC;
    #pragma unroll
    for (int nf = 0; nf < 16; nf++) {
        int n = ch * 128 + nf * 8 + ncol;
        float2 gA = __half22float2(*(const __half2*)&g_Gh[gm0 + n]);
        float2 gB = __half22float2(*(const __half2*)&g_Gh[gm1 + n]);
        *(uint32_t*)&g_Ph[gm0 + n] =
            pack2h(acc[nf][0] * inv0 * gA.x, acc[nf][1] * inv0 * gA.y);
        *(uint32_t*)&g_Ph[gm1 + n] =
            pack2h(acc[nf][2] * inv1 * gB.x, acc[nf][3] * inv1 * gB.y);
    }
}

// ---------------------------------------------------------------------------
// out_gemm: single-stage full-K (256). A, B, X all prefetched via cp.async at
// kernel start; one sync; 16 uninterrupted k-steps; epilogue reads X from SMEM.
// 1 CTA/SM (203 KB smem), grid (64, 8).
// ---------------------------------------------------------------------------
#define OG_PITCH  528                    // 256 fp16 + 16B pad
#define OG_TILE   (128 * OG_PITCH)       // 67584
#define OG_A      0
#define OG_B      OG_TILE
#define OG_X      (2 * OG_TILE)          // X fp32, pitch 132 floats (528B)
#define OG_SMEM   (3 * OG_TILE)          // 202752

__global__ __launch_bounds__(256) void out_gemm(
    const float* __restrict__ X, const float* __restrict__ bp,
    float* __restrict__ outp)
{
    extern __shared__ char smraw[];
    uint32_t sbase = smem_u32(smraw);
    const int tid = threadIdx.x;
    const int m0 = blockIdx.x * 128;
    const int n0 = blockIdx.y * 128;

    const __half* A = g_Ph + (size_t)m0 * DVC;
    const __half* B = g_Wpt + (size_t)n0 * DVC;

    // Group 1: A + B (128 rows x 32 segs of 16B each)
    #pragma unroll
    for (int i = 0; i < 16; i++) {
        int idx = tid + i * 256;          // 0..4095
        int row = idx >> 5, seg = idx & 31;
        uint32_t so = row * OG_PITCH + seg * 16;
        CPA16(sbase + OG_A + so, A + (size_t)row * DVC + seg * 8);
        CPA16(sbase + OG_B + so, B + (size_t)row * DVC + seg * 8);
    }
    CP_COMMIT();
    // Group 2: X tile (128 rows x 128 fp32 = 32 segs of 16B)
    #pragma unroll
    for (int i = 0; i < 16; i++) {
        int idx = tid + i * 256;
        int row = idx >> 5, seg = idx & 31;
        CPA16(sbase + OG_X + row * OG_PITCH + seg * 16,
              X + (size_t)(m0 + row) * DD + n0 + seg * 4);
    }
    CP_COMMIT();

    const int warp = tid >> 5, lane = tid & 31;
    const int lr = lane & 7, gq = lane >> 3;
    const int wm = (warp & 1) * 64, wn = (warp >> 1) * 32;
    const uint32_t a_off = sbase + OG_A +
        (wm + lr + (gq & 1) * 8) * OG_PITCH + (gq >> 1) * 16;
    const uint32_t b_off = sbase + OG_B +
        (wn + lr + (gq >> 1) * 8) * OG_PITCH + (gq & 1) * 16;

    float acc[4][4][4] = {};

    CP_WAIT1();          // A + B ready
    __syncthreads();

    #pragma unroll
    for (int ks = 0; ks < 16; ks++) {
        uint32_t ah[4][4], bh[2][4];
        #pragma unroll
        for (int mf = 0; mf < 4; mf++)
            LDSM4(ah[mf], a_off + mf * 16 * OG_PITCH + ks * 32);
        #pragma unroll
        for (int np = 0; np < 2; np++)
            LDSM4(bh[np], b_off + np * 16 * OG_PITCH + ks * 32);
        #pragma unroll
        for (int mf = 0; mf < 4; mf++) {
            #pragma unroll
            for (int nf = 0; nf < 4; nf++) {
                MMA16816(acc[mf][nf], ah[mf],
                         bh[nf >> 1][(nf & 1) * 2], bh[nf >> 1][(nf & 1) * 2 + 1]);
            }
        }
    }

    CP_WAIT0();          // X ready (long since landed)
    __syncthreads();

    const float* sx = (const float*)(smraw + OG_X);
    const int mrow = lane >> 2, ncol = (lane & 3) * 2;
    #pragma unroll
    for (int mf = 0; mf < 4; mf++) {
        #pragma unroll
        for (int nf = 0; nf < 4; nf++) {
            int lm = wm + mf * 16 + mrow;
            int ln = wn + nf * 8 + ncol;
            int m = m0 + lm;
            int n = n0 + ln;
            float b0 = bp[n], b1 = bp[n + 1];
            float2 x0 = *(const float2*)&sx[lm * 132 + ln];
            float2 x1 = *(const float2*)&sx[(lm + 8) * 132 + ln];
            *(float2*)&outp[(size_t)m * DD + n] =
                make_float2(acc[mf][nf][0] + b0 + x0.x, acc[mf][nf][1] + b1 + x0.y);
            *(float2*)&outp[(size_t)(m + 8) * DD + n] =
                make_float2(acc[mf][nf][2] + b0 + x1.x, acc[mf][nf][3] + b1 + x1.y);
        }
    }
}

// ---------------------------------------------------------------------------
extern "C" void kernel_launch(void* const* d_in, const int* in_sizes, int n_in,
                              void* d_out, int out_size)
{
    const float* X  = (const float*)d_in[0];
    const float* Wq = (const float*)d_in[1];
    const float* bq = (const float*)d_in[2];
    const float* Wk = (const float*)d_in[3];
    const float* bk = (const float*)d_in[4];
    const float* Wv = (const float*)d_in[5];
    const float* bv = (const float*)d_in[6];
    const float* Wg = (const float*)d_in[7];
    const float* bg = (const float*)d_in[8];
    const float* Wp = (const float*)d_in[9];
    const float* bp = (const float*)d_in[10];
    float* out = (float*)d_out;

    cudaFuncSetAttribute(proj_gemm, cudaFuncAttributeMaxDynamicSharedMemorySize, GEMM_SMEM_BYTES);
    cudaFuncSetAttribute(out_gemm,  cudaFuncAttributeMaxDynamicSharedMemorySize, OG_SMEM);
    cudaFuncSetAttribute(attn_kernel, cudaFuncAttributeMaxDynamicSharedMemorySize, ATT_SMEM_BYTES);

    prep_kernel<<<XB + WB, 256>>>(X, Wq, Wk, Wv, Wg, Wp);
    proj_gemm<<<dim3(64, 6), 256, GEMM_SMEM_BYTES>>>(bq, bk, bv, bg);
    attn_kernel<<<128, 256, ATT_SMEM_BYTES>>>();
    out_gemm<<<dim3(64, 8), 256, OG_SMEM>>>(X, bp, out);
}

// round 15
// speedup vs baseline: 1.0237x; 1.0237x over previous
#include <cuda_runtime.h>
#include <cuda_fp16.h>
#include <cstdint>

#define BB   4
#define SS   2048
#define DD   1024
#define DQKC 128
#define DVC  256
#define MM   (BB * SS)   // 8192
#define NPROJ 768

// ---------------------------------------------------------------------------
// Device scratch (all fp16 operands)
// ---------------------------------------------------------------------------
__device__ __align__(256) __half g_Xh[MM * DD];
__device__ __align__(256) __half g_Wt[NPROJ * DD];      // [n][k]
__device__ __align__(256) __half g_Wpt[DD * DVC];       // [n][k]
__device__ __align__(256) __half g_Qh[MM * DQKC];
__device__ __align__(256) __half g_Kh[MM * DQKC];
__device__ __align__(256) __half g_Vt[BB * DVC * SS];   // [b][n][s]
__device__ __align__(256) __half g_Gh[MM * DVC];
__device__ __align__(256) __half g_Ph[MM * DVC];        // (AV*G)
__device__ __align__(256) float g_Q2[MM];
__device__ __align__(256) float g_K2[MM];

// ---------------------------------------------------------------------------
// PTX helpers
// ---------------------------------------------------------------------------
__device__ __forceinline__ uint32_t smem_u32(const void* p) {
    uint32_t a;
    asm("{ .reg .u64 t; cvta.to.shared.u64 t, %1; cvt.u32.u64 %0, t; }"
        : "=r"(a) : "l"(p));
    return a;
}

#define LDSM4(r, addr) \
    asm volatile("ldmatrix.sync.aligned.m8n8.x4.shared.b16 {%0,%1,%2,%3}, [%4];" \
        : "=r"((r)[0]), "=r"((r)[1]), "=r"((r)[2]), "=r"((r)[3]) : "r"(addr))

#define MMA16816(c, a, b0, b1) \
    asm volatile("mma.sync.aligned.m16n8k16.row.col.f32.f16.f16.f32 " \
        "{%0,%1,%2,%3}, {%4,%5,%6,%7}, {%8,%9}, {%0,%1,%2,%3};" \
        : "+f"((c)[0]), "+f"((c)[1]), "+f"((c)[2]), "+f"((c)[3]) \
        : "r"((a)[0]), "r"((a)[1]), "r"((a)[2]), "r"((a)[3]), "r"(b0), "r"(b1))

#define CPA16(s, g) \
    asm volatile("cp.async.ca.shared.global [%0], [%1], 16;" :: "r"(s), "l"(g) : "memory")
#define CP_COMMIT() asm volatile("cp.async.commit_group;" ::: "memory")
#define CP_WAIT0()  asm volatile("cp.async.wait_group 0;" ::: "memory")
#define CP_WAIT1()  asm volatile("cp.async.wait_group 1;" ::: "memory")
#define CP_WAIT4()  asm volatile("cp.async.wait_group 4;" ::: "memory")
#define CP_WAIT5()  asm volatile("cp.async.wait_group 5;" ::: "memory")

#define PREFETCH_L2(p) asm volatile("prefetch.global.L2 [%0];" :: "l"(p))

__device__ __forceinline__ uint32_t pack2h(float a, float b) {
    __half2 hp(__float2half_rn(a), __float2half_rn(b));
    return *reinterpret_cast<uint32_t*>(&hp);
}

// ---------------------------------------------------------------------------
// Prep: blocks [0, XB) convert X; blocks [XB, XB+1024) transpose weights via
// 32x32 SMEM tiles (coalesced fp32 reads, coalesced fp16 writes).
//   tiles 0..127   Wq -> g_Wt rows [0,128)
//   tiles 128..255 Wk -> g_Wt rows [128,256)
//   tiles 256..511 Wv -> g_Wt rows [256,512)
//   tiles 512..767 Wg -> g_Wt rows [512,768)
//   tiles 768..1023 Wp -> g_Wpt
// ---------------------------------------------------------------------------
#define XB (MM * DD / 1024)     // 8192
#define WTILES 1024

__global__ __launch_bounds__(256) void prep_kernel(
    const float* __restrict__ X,
    const float* __restrict__ Wq, const float* __restrict__ Wk,
    const float* __restrict__ Wv, const float* __restrict__ Wg,
    const float* __restrict__ Wp)
{
    const int tid = threadIdx.x;
    if (blockIdx.x < XB) {
        int i = (blockIdx.x * 256 + tid) * 4;
        float4 v = *(const float4*)&X[i];
        *(uint2*)&g_Xh[i] = make_uint2(pack2h(v.x, v.y), pack2h(v.z, v.w));
        return;
    }
    __shared__ float ts[32][33];
    int t = blockIdx.x - XB;
    const float* src; __half* dst;
    int srcN, dstStride, nbase, tilesN;
    if (t < 128)      { src = Wq; srcN = 128;  dst = g_Wt;  dstStride = DD;  nbase = 0;   tilesN = 4;  }
    else if (t < 256) { src = Wk; srcN = 128;  dst = g_Wt;  dstStride = DD;  nbase = 128; tilesN = 4;  t -= 128; }
    else if (t < 512) { src = Wv; srcN = 256;  dst = g_Wt;  dstStride = DD;  nbase = 256; tilesN = 8;  t -= 256; }
    else if (t < 768) { src = Wg; srcN = 256;  dst = g_Wt;  dstStride = DD;  nbase = 512; tilesN = 8;  t -= 512; }
    else              { src = Wp; srcN = 1024; dst = g_Wpt; dstStride = DVC; nbase = 0;   tilesN = 32; t -= 768; }
    const int k0 = (t / tilesN) * 32;
    const int n0 = (t % tilesN) * 32;
    const int tx = tid & 31, ty = tid >> 5;
    #pragma unroll
    for (int r = 0; r < 4; r++)
        ts[ty + r * 8][tx] = src[(size_t)(k0 + ty + r * 8) * srcN + n0 + tx];
    __syncthreads();
    #pragma unroll
    for (int r = 0; r < 4; r++)
        dst[(size_t)(nbase + n0 + ty + r * 8) * dstStride + k0 + tx] =
            __float2half_rn(ts[tx][ty + r * 8]);
}

// ---------------------------------------------------------------------------
// GEMM machinery: single fp16, BK=64, pitch-144 tiles, 2 stages.
// ---------------------------------------------------------------------------
#define TILE_BYTES   18432
#define STAGE_BYTES  (2 * TILE_BYTES)
#define GEMM_SMEM_BYTES (2 * STAGE_BYTES)

__device__ __forceinline__ void stage_copy(
    uint32_t sstage,
    const __half* __restrict__ A, int lda,
    const __half* __restrict__ B, int ldb, int k0, int tid)
{
    #pragma unroll
    for (int i = 0; i < 4; i++) {
        int idx = tid + i * 256;
        int row = idx >> 3;
        int seg = idx & 7;
        uint32_t so = row * 144 + seg * 16;
        CPA16(sstage +              so, A + (size_t)row * lda + k0 + seg * 8);
        CPA16(sstage + TILE_BYTES + so, B + (size_t)row * ldb + k0 + seg * 8);
    }
}

__device__ __forceinline__ void compute_stage(
    uint32_t sstage, uint32_t a_off, uint32_t b_off, float acc[4][4][4])
{
    #pragma unroll
    for (int ks = 0; ks < 4; ks++) {
        uint32_t ah[4][4], bh[2][4];
        #pragma unroll
        for (int mf = 0; mf < 4; mf++)
            LDSM4(ah[mf], sstage + a_off + mf * 2304 + ks * 32);
        #pragma unroll
        for (int np = 0; np < 2; np++)
            LDSM4(bh[np], sstage + TILE_BYTES + b_off + np * 2304 + ks * 32);
        #pragma unroll
        for (int mf = 0; mf < 4; mf++) {
            #pragma unroll
            for (int nf = 0; nf < 4; nf++) {
                MMA16816(acc[mf][nf], ah[mf],
                         bh[nf >> 1][(nf & 1) * 2], bh[nf >> 1][(nf & 1) * 2 + 1]);
            }
        }
    }
}

// ---------------------------------------------------------------------------
// proj_gemm: grid (64, 6), 256 threads, 2 CTAs/SM. Fused epilogues.
// ---------------------------------------------------------------------------
__global__ __launch_bounds__(256, 2) void proj_gemm(
    const float* __restrict__ bq, const float* __restrict__ bk,
    const float* __restrict__ bv, const float* __restrict__ bg)
{
    extern __shared__ char smraw[];
    __shared__ float sq2[128];
    uint32_t sbase = smem_u32(smraw);
    const int tid = threadIdx.x;
    const int m0 = blockIdx.x * 128;
    const int slab = blockIdx.y;
    const int nbase = slab * 128;

    if (tid < 128) sq2[tid] = 0.0f;

    const __half* A = g_Xh + (size_t)m0 * DD;
    const __half* B = g_Wt + (size_t)nbase * DD;

    const int warp = tid >> 5, lane = tid & 31;
    const int lr = lane & 7, gq = lane >> 3;
    const int wm = (warp & 1) * 64, wn = (warp >> 1) * 32;
    const uint32_t a_off = (wm + lr + (gq & 1) * 8) * 144 + (gq >> 1) * 16;
    const uint32_t b_off = (wn + lr + (gq >> 1) * 8) * 144 + (gq & 1) * 16;

    float acc[4][4][4] = {};

    stage_copy(sbase, A, DD, B, DD, 0, tid);
    CP_COMMIT();
    for (int kb = 0; kb < 16; kb++) {
        if (kb + 1 < 16) {
            stage_copy(sbase + ((kb + 1) & 1) * STAGE_BYTES,
                       A, DD, B, DD, (kb + 1) * 64, tid);
            CP_COMMIT();
            CP_WAIT1();
        } else {
            CP_WAIT0();
        }
        __syncthreads();
        compute_stage(sbase + (kb & 1) * STAGE_BYTES, a_off, b_off, acc);
        __syncthreads();
    }

    const int mrow = lane >> 2, ncol = (lane & 3) * 2;

    if (slab < 2) {
        const float* bias = (slab == 0) ? bq : bk;
        __half* dst = (slab == 0) ? g_Qh : g_Kh;
        float part[4][2] = {};
        #pragma unroll
        for (int mf = 0; mf < 4; mf++) {
            int lm = wm + mf * 16 + mrow;
            #pragma unroll
            for (int nf = 0; nf < 4; nf++) {
                int n = wn + nf * 8 + ncol;
                float b0 = bias[n], b1 = bias[n + 1];
                __half h00 = __float2half_rn(acc[mf][nf][0] + b0);
                __half h01 = __float2half_rn(acc[mf][nf][1] + b1);
                __half h10 = __float2half_rn(acc[mf][nf][2] + b0);
                __half h11 = __float2half_rn(acc[mf][nf][3] + b1);
                __half2 p0(h00, h01), p1(h10, h11);
                *(uint32_t*)&dst[(size_t)(m0 + lm) * DQKC + n] =
                    *reinterpret_cast<uint32_t*>(&p0);
                *(uint32_t*)&dst[(size_t)(m0 + lm + 8) * DQKC + n] =
                    *reinterpret_cast<uint32_t*>(&p1);
                float f00 = __half2float(h00), f01 = __half2float(h01);
                float f10 = __half2float(h10), f11 = __half2float(h11);
                part[mf][0] += f00 * f00 + f01 * f01;
                part[mf][1] += f10 * f10 + f11 * f11;
            }
        }
        #pragma unroll
        for (int mf = 0; mf < 4; mf++) {
            float s0 = part[mf][0], s1 = part[mf][1];
            s0 += __shfl_xor_sync(0xffffffffu, s0, 1);
            s0 += __shfl_xor_sync(0xffffffffu, s0, 2);
            s1 += __shfl_xor_sync(0xffffffffu, s1, 1);
            s1 += __shfl_xor_sync(0xffffffffu, s1, 2);
            if ((lane & 3) == 0) {
                int lm = wm + mf * 16 + mrow;
                atomicAdd(&sq2[lm], s0);
                atomicAdd(&sq2[lm + 8], s1);
            }
        }
        __syncthreads();
        if (tid < 128) {
            if (slab == 0) g_Q2[m0 + tid] = sq2[tid];
            else           g_K2[m0 + tid] = sq2[tid];
        }
    } else if (slab < 4) {
        __half* Vs = (__half*)smraw;
        const int VSP = 130;
        #pragma unroll
        for (int mf = 0; mf < 4; mf++) {
            int lm = wm + mf * 16 + mrow;
            #pragma unroll
            for (int nf = 0; nf < 4; nf++) {
                int n = wn + nf * 8 + ncol;
                float b0 = bv[((slab == 3) ? 128 : 0) + n];
                float b1 = bv[((slab == 3) ? 128 : 0) + n + 1];
                *(uint32_t*)&Vs[lm * VSP + n] =
                    pack2h(acc[mf][nf][0] + b0, acc[mf][nf][1] + b1);
                *(uint32_t*)&Vs[(lm + 8) * VSP + n] =
                    pack2h(acc[mf][nf][2] + b0, acc[mf][nf][3] + b1);
            }
        }
        __syncthreads();
        const int batch = m0 >> 11;
        const int mloc  = m0 & 2047;
        const int nbo   = (slab == 3) ? 128 : 0;
        #pragma unroll
        for (int i = 0; i < 8; i++) {
            int idx = tid + i * 256;
            int n = idx >> 4;
            int mseg = idx & 15;
            __half tmp[8];
            #pragma unroll
            for (int j = 0; j < 8; j++)
                tmp[j] = Vs[(mseg * 8 + j) * VSP + n];
            *(uint4*)&g_Vt[((size_t)batch * DVC + nbo + n) * SS + mloc + mseg * 8] =
                *(uint4*)tmp;
        }
    } else {
        const int nbo = (slab == 5) ? 128 : 0;
        #pragma unroll
        for (int mf = 0; mf < 4; mf++) {
            int m = m0 + wm + mf * 16 + mrow;
            #pragma unroll
            for (int nf = 0; nf < 4; nf++) {
                int n = wn + nf * 8 + ncol;
                float b0 = bg[nbo + n], b1 = bg[nbo + n + 1];
                *(uint32_t*)&g_Gh[(size_t)m * DVC + nbo + n] =
                    pack2h(acc[mf][nf][0] + b0, acc[mf][nf][1] + b1);
                *(uint32_t*)&g_Gh[(size_t)(m + 8) * DVC + nbo + n] =
                    pack2h(acc[mf][nf][2] + b0, acc[mf][nf][3] + b1);
            }
        }
    }
}

// ---------------------------------------------------------------------------
// attn: register-resident w (R13, unchanged).
// ---------------------------------------------------------------------------
#define QPITCH 272
#define KPITCH 272
#define VPITCH 144

#define KBUF_BYTES 17408
#define VBUF_BYTES 36864

#define OFF_QH  0
#define OFF_KH  17408
#define OFF_VH  69632
#define OFF_K2  180224
#define ATT_SMEM_BYTES 180992

#define WSCALE 1024.0f

__device__ __forceinline__ void attn_load_k(uint32_t sKh, int krow0c, int tid)
{
    #pragma unroll
    for (int i = 0; i < 4; i++) {
        int idx = tid + i * 256;
        int row = idx >> 4, seg = idx & 15;
        CPA16(sKh + row * KPITCH + seg * 16,
              g_Kh + (size_t)(krow0c + row) * DQKC + seg * 8);
    }
}

__device__ __forceinline__ void attn_load_v(uint32_t sVh, int b, int kb, int tid)
{
    #pragma unroll
    for (int i = 0; i < 8; i++) {
        int idx = tid + i * 256;
        int n = idx >> 3, seg = idx & 7;
        CPA16(sVh + n * VPITCH + seg * 16,
              g_Vt + ((size_t)b * DVC + n) * (size_t)SS + kb * 64 + seg * 8);
    }
}

__global__ __launch_bounds__(256) void attn_kernel()
{
    extern __shared__ char smc[];
    const uint32_t sb = smem_u32(smc);

    const int tid  = threadIdx.x;
    const int warp = tid >> 5, lane = tid & 31;
    const int lr = lane & 7, gq = lane >> 3;
    const int mrow = lane >> 2, ncol = (lane & 3) * 2;
    const int rg = warp & 3;
    const int ch = warp >> 2;

    const int b  = blockIdx.x >> 5;
    const int qt = blockIdx.x & 31;
    const int qrow0 = b * SS + qt * 64;
    const int krow0 = b * SS;

    #pragma unroll
    for (int i = 0; i < 4; i++) {
        int idx = tid + i * 256;
        int row = idx >> 4, seg = idx & 15;
        CPA16(sb + OFF_QH + row * QPITCH + seg * 16,
              g_Qh + (size_t)(qrow0 + row) * DQKC + seg * 8);
    }
    attn_load_k(sb + OFF_KH, krow0, tid);
    if (tid < 16) CPA16(sb + OFF_K2 + tid * 16, g_K2 + krow0 + tid * 4);
    CP_COMMIT();
    attn_load_v(sb + OFF_VH, b, 0, tid);
    CP_COMMIT();
    attn_load_k(sb + OFF_KH + KBUF_BYTES, krow0 + 64, tid);
    if (tid < 16) CPA16(sb + OFF_K2 + 256 + tid * 16, g_K2 + krow0 + 64 + tid * 4);
    CP_COMMIT();
    attn_load_v(sb + OFF_VH + VBUF_BYTES, b, 1, tid);
    CP_COMMIT();

    const int r0 = rg * 16 + mrow;
    const float q20 = g_Q2[qrow0 + r0];
    const float q21 = g_Q2[qrow0 + r0 + 8];
    float rs0 = 0.0f, rs1 = 0.0f;

    const uint32_t aQbase = sb + OFF_QH +
        (rg * 16 + lr + (gq & 1) * 8) * QPITCH + (gq >> 1) * 16;
    const uint32_t bK = (lr + (gq >> 1) * 8) * KPITCH + (gq & 1) * 16;
    const uint32_t bV = (ch * 128 + lr + (gq >> 1) * 8) * VPITCH + (gq & 1) * 16;

    float acc[16][4] = {};

    for (int kc = 0; kc < 32; kc++) {
        __syncthreads();

        if (kc + 2 < 32) {
            int j = (kc + 2) % 3;
            attn_load_k(sb + OFF_KH + j * KBUF_BYTES, krow0 + (kc + 2) * 64, tid);
            if (tid < 16) CPA16(sb + OFF_K2 + j * 256 + tid * 16,
                                g_K2 + krow0 + (kc + 2) * 64 + tid * 4);
        }
        CP_COMMIT();
        if (kc + 2 < 32) {
            int j = (kc + 2) % 3;
            attn_load_v(sb + OFF_VH + j * VBUF_BYTES, b, kc + 2, tid);
        }
        CP_COMMIT();

        CP_WAIT5();

        const uint32_t sKH = sb + OFF_KH + (kc % 3) * KBUF_BYTES + bK;
        float s[8][4];
        #pragma unroll
        for (int nt = 0; nt < 8; nt++)
            #pragma unroll
            for (int k = 0; k < 4; k++) s[nt][k] = 0.0f;
        #pragma unroll
        for (int ks = 0; ks < 8; ks++) {
            uint32_t ah[4], bh[4][4];
            LDSM4(ah, aQbase + ks * 32);
            #pragma unroll
            for (int np = 0; np < 4; np++)
                LDSM4(bh[np], sKH + np * 16 * KPITCH + ks * 32);
            #pragma unroll
            for (int nt = 0; nt < 8; nt++)
                MMA16816(s[nt], ah, bh[nt >> 1][(nt & 1) * 2],
                         bh[nt >> 1][(nt & 1) * 2 + 1]);
        }

        const float* k2c = (const float*)(smc + OFF_K2 + (kc % 3) * 256);
        uint32_t wf[4][4];
        #pragma unroll
        for (int nt = 0; nt < 8; nt++) {
            float k20 = k2c[nt * 8 + ncol], k21 = k2c[nt * 8 + ncol + 1];
            float d00 = fmaxf(fmaf(-2.0f, s[nt][0], q20 + k20), 1e-6f);
            float d01 = fmaxf(fmaf(-2.0f, s[nt][1], q20 + k21), 1e-6f);
            float d10 = fmaxf(fmaf(-2.0f, s[nt][2], q21 + k20), 1e-6f);
            float d11 = fmaxf(fmaf(-2.0f, s[nt][3], q21 + k21), 1e-6f);
            float w00 = __fdividef(WSCALE, d00);
            float w01 = __fdividef(WSCALE, d01);
            float w10 = __fdividef(WSCALE, d10);
            float w11 = __fdividef(WSCALE, d11);
            rs0 += w00 + w01;
            rs1 += w10 + w11;
            int ks = nt >> 1, ix = (nt & 1) * 2;
            wf[ks][ix]     = pack2h(w00, w01);
            wf[ks][ix + 1] = pack2h(w10, w11);
        }

        CP_WAIT4();

        const uint32_t sVH = sb + OFF_VH + (kc % 3) * VBUF_BYTES + bV;
        #pragma unroll
        for (int ks = 0; ks < 4; ks++) {
            uint32_t bvh[8][4];
            #pragma unroll
            for (int nn = 0; nn < 8; nn++)
                LDSM4(bvh[nn], sVH + nn * 16 * VPITCH + ks * 32);
            #pragma unroll
            for (int nf = 0; nf < 16; nf++)
                MMA16816(acc[nf], wf[ks], bvh[nf >> 1][(nf & 1) * 2],
                         bvh[nf >> 1][(nf & 1) * 2 + 1]);
        }
    }

    rs0 += __shfl_xor_sync(0xffffffffu, rs0, 1);
    rs0 += __shfl_xor_sync(0xffffffffu, rs0, 2);
    rs1 += __shfl_xor_sync(0xffffffffu, rs1, 1);
    rs1 += __shfl_xor_sync(0xffffffffu, rs1, 2);
    const float inv0 = 1.0f / rs0;
    const float inv1 = 1.0f / rs1;
    const size_t gm0 = (size_t)(qrow0 + r0) * DVC;
    const size_t gm1 = gm0 + 8 * DVC;
    #pragma unroll
    for (int nf = 0; nf < 16; nf++) {
        int n = ch * 128 + nf * 8 + ncol;
        float2 gA = __half22float2(*(const __half2*)&g_Gh[gm0 + n]);
        float2 gB = __half22float2(*(const __half2*)&g_Gh[gm1 + n]);
        *(uint32_t*)&g_Ph[gm0 + n] =
            pack2h(acc[nf][0] * inv0 * gA.x, acc[nf][1] * inv0 * gA.y);
        *(uint32_t*)&g_Ph[gm1 + n] =
            pack2h(acc[nf][2] * inv1 * gB.x, acc[nf][3] * inv1 * gB.y);
    }
}

// ---------------------------------------------------------------------------
// out_gemm: R13 form (BK=64, 2 stages, 2 CTAs/SM) + L2 prefetch of X tile.
// ---------------------------------------------------------------------------
__global__ __launch_bounds__(256, 2) void out_gemm(
    const float* __restrict__ X, const float* __restrict__ bp,
    float* __restrict__ outp)
{
    extern __shared__ char smraw[];
    uint32_t sbase = smem_u32(smraw);
    const int tid = threadIdx.x;
    const int m0 = blockIdx.x * 128;
    const int n0 = blockIdx.y * 128;

    // Warm L2 with this CTA's X residual tile (512 x 128B lines).
    #pragma unroll
    for (int i = 0; i < 2; i++) {
        int idx = tid + i * 256;         // 0..511
        int row = idx >> 2, seg = idx & 3;
        PREFETCH_L2(X + (size_t)(m0 + row) * DD + n0 + seg * 32);
    }

    const __half* A = g_Ph + (size_t)m0 * DVC;
    const __half* B = g_Wpt + (size_t)n0 * DVC;

    const int warp = tid >> 5, lane = tid & 31;
    const int lr = lane & 7, gq = lane >> 3;
    const int wm = (warp & 1) * 64, wn = (warp >> 1) * 32;
    const uint32_t a_off = (wm + lr + (gq & 1) * 8) * 144 + (gq >> 1) * 16;
    const uint32_t b_off = (wn + lr + (gq >> 1) * 8) * 144 + (gq & 1) * 16;

    float acc[4][4][4] = {};

    stage_copy(sbase, A, DVC, B, DVC, 0, tid);
    CP_COMMIT();
    for (int kb = 0; kb < 4; kb++) {
        if (kb + 1 < 4) {
            stage_copy(sbase + ((kb + 1) & 1) * STAGE_BYTES,
                       A, DVC, B, DVC, (kb + 1) * 64, tid);
            CP_COMMIT();
            CP_WAIT1();
        } else {
            CP_WAIT0();
        }
        __syncthreads();
        compute_stage(sbase + (kb & 1) * STAGE_BYTES, a_off, b_off, acc);
        __syncthreads();
    }

    const int mrow = lane >> 2, ncol = (lane & 3) * 2;
    #pragma unroll
    for (int mf = 0; mf < 4; mf++) {
        #pragma unroll
        for (int nf = 0; nf < 4; nf++) {
            int m = m0 + wm + mf * 16 + mrow;
            int n = n0 + wn + nf * 8 + ncol;
            float b0 = bp[n], b1 = bp[n + 1];
            float2 x0 = *(const float2*)&X[(size_t)m * DD + n];
            float2 x1 = *(const float2*)&X[(size_t)(m + 8) * DD + n];
            *(float2*)&outp[(size_t)m * DD + n] =
                make_float2(acc[mf][nf][0] + b0 + x0.x, acc[mf][nf][1] + b1 + x0.y);
            *(float2*)&outp[(size_t)(m + 8) * DD + n] =
                make_float2(acc[mf][nf][2] + b0 + x1.x, acc[mf][nf][3] + b1 + x1.y);
        }
    }
}

// ---------------------------------------------------------------------------
extern "C" void kernel_launch(void* const* d_in, const int* in_sizes, int n_in,
                              void* d_out, int out_size)
{
    const float* X  = (const float*)d_in[0];
    const float* Wq = (const float*)d_in[1];
    const float* bq = (const float*)d_in[2];
    const float* Wk = (const float*)d_in[3];
    const float* bk = (const float*)d_in[4];
    const float* Wv = (const float*)d_in[5];
    const float* bv = (const float*)d_in[6];
    const float* Wg = (const float*)d_in[7];
    const float* bg = (const float*)d_in[8];
    const float* Wp = (const float*)d_in[9];
    const float* bp = (const float*)d_in[10];
    float* out = (float*)d_out;

    cudaFuncSetAttribute(proj_gemm, cudaFuncAttributeMaxDynamicSharedMemorySize, GEMM_SMEM_BYTES);
    cudaFuncSetAttribute(out_gemm,  cudaFuncAttributeMaxDynamicSharedMemorySize, GEMM_SMEM_BYTES);
    cudaFuncSetAttribute(attn_kernel, cudaFuncAttributeMaxDynamicSharedMemorySize, ATT_SMEM_BYTES);

    prep_kernel<<<XB + WTILES, 256>>>(X, Wq, Wk, Wv, Wg, Wp);
    proj_gemm<<<dim3(64, 6), 256, GEMM_SMEM_BYTES>>>(bq, bk, bv, bg);
    attn_kernel<<<128, 256, ATT_SMEM_BYTES>>>();
    out_gemm<<<dim3(64, 8), 256, GEMM_SMEM_BYTES>>>(X, bp, out);
}

// round 16
// speedup vs baseline: 1.0486x; 1.0243x over previous
#include <cuda_runtime.h>
#include <cuda_fp16.h>
#include <cstdint>

#define BB   4
#define SS   2048
#define DD   1024
#define DQKC 128
#define DVC  256
#define MM   (BB * SS)   // 8192
#define NPROJ 768

// ---------------------------------------------------------------------------
// Device scratch (all fp16 operands)
// ---------------------------------------------------------------------------
__device__ __align__(256) __half g_Xh[MM * DD];
__device__ __align__(256) __half g_Wt[NPROJ * DD];      // [n][k]
__device__ __align__(256) __half g_Wpt[DD * DVC];       // [n][k]
__device__ __align__(256) __half g_Qh[MM * DQKC];
__device__ __align__(256) __half g_Kh[MM * DQKC];
__device__ __align__(256) __half g_Vt[BB * DVC * SS];   // [b][n][s]
__device__ __align__(256) __half g_Gh[MM * DVC];
__device__ __align__(256) __half g_Ph[MM * DVC];        // (AV*G)
__device__ __align__(256) float g_Q2[MM];
__device__ __align__(256) float g_K2[MM];

// ---------------------------------------------------------------------------
// PTX helpers
// ---------------------------------------------------------------------------
__device__ __forceinline__ uint32_t smem_u32(const void* p) {
    uint32_t a;
    asm("{ .reg .u64 t; cvta.to.shared.u64 t, %1; cvt.u32.u64 %0, t; }"
        : "=r"(a) : "l"(p));
    return a;
}

#define LDSM4(r, addr) \
    asm volatile("ldmatrix.sync.aligned.m8n8.x4.shared.b16 {%0,%1,%2,%3}, [%4];" \
        : "=r"((r)[0]), "=r"((r)[1]), "=r"((r)[2]), "=r"((r)[3]) : "r"(addr))

#define MMA16816(c, a, b0, b1) \
    asm volatile("mma.sync.aligned.m16n8k16.row.col.f32.f16.f16.f32 " \
        "{%0,%1,%2,%3}, {%4,%5,%6,%7}, {%8,%9}, {%0,%1,%2,%3};" \
        : "+f"((c)[0]), "+f"((c)[1]), "+f"((c)[2]), "+f"((c)[3]) \
        : "r"((a)[0]), "r"((a)[1]), "r"((a)[2]), "r"((a)[3]), "r"(b0), "r"(b1))

#define CPA16(s, g) \
    asm volatile("cp.async.ca.shared.global [%0], [%1], 16;" :: "r"(s), "l"(g) : "memory")
#define CP_COMMIT() asm volatile("cp.async.commit_group;" ::: "memory")
#define CP_WAIT0()  asm volatile("cp.async.wait_group 0;" ::: "memory")
#define CP_WAIT1()  asm volatile("cp.async.wait_group 1;" ::: "memory")
#define CP_WAIT4()  asm volatile("cp.async.wait_group 4;" ::: "memory")
#define CP_WAIT5()  asm volatile("cp.async.wait_group 5;" ::: "memory")

__device__ __forceinline__ uint32_t pack2h(float a, float b) {
    __half2 hp(__float2half_rn(a), __float2half_rn(b));
    return *reinterpret_cast<uint32_t*>(&hp);
}

// ---------------------------------------------------------------------------
// Prep: blocks [0, XB) convert X; blocks [XB, XB+1024) transpose weights via
// 32x32 SMEM tiles (coalesced fp32 reads, coalesced fp16 writes).
// ---------------------------------------------------------------------------
#define XB (MM * DD / 1024)     // 8192
#define WTILES 1024

__global__ __launch_bounds__(256) void prep_kernel(
    const float* __restrict__ X,
    const float* __restrict__ Wq, const float* __restrict__ Wk,
    const float* __restrict__ Wv, const float* __restrict__ Wg,
    const float* __restrict__ Wp)
{
    const int tid = threadIdx.x;
    if (blockIdx.x < XB) {
        int i = (blockIdx.x * 256 + tid) * 4;
        float4 v = *(const float4*)&X[i];
        *(uint2*)&g_Xh[i] = make_uint2(pack2h(v.x, v.y), pack2h(v.z, v.w));
        return;
    }
    __shared__ float ts[32][33];
    int t = blockIdx.x - XB;
    const float* src; __half* dst;
    int srcN, dstStride, nbase, tilesN;
    if (t < 128)      { src = Wq; srcN = 128;  dst = g_Wt;  dstStride = DD;  nbase = 0;   tilesN = 4;  }
    else if (t < 256) { src = Wk; srcN = 128;  dst = g_Wt;  dstStride = DD;  nbase = 128; tilesN = 4;  t -= 128; }
    else if (t < 512) { src = Wv; srcN = 256;  dst = g_Wt;  dstStride = DD;  nbase = 256; tilesN = 8;  t -= 256; }
    else if (t < 768) { src = Wg; srcN = 256;  dst = g_Wt;  dstStride = DD;  nbase = 512; tilesN = 8;  t -= 512; }
    else              { src = Wp; srcN = 1024; dst = g_Wpt; dstStride = DVC; nbase = 0;   tilesN = 32; t -= 768; }
    const int k0 = (t / tilesN) * 32;
    const int n0 = (t % tilesN) * 32;
    const int tx = tid & 31, ty = tid >> 5;
    #pragma unroll
    for (int r = 0; r < 4; r++)
        ts[ty + r * 8][tx] = src[(size_t)(k0 + ty + r * 8) * srcN + n0 + tx];
    __syncthreads();
    #pragma unroll
    for (int r = 0; r < 4; r++)
        dst[(size_t)(nbase + n0 + ty + r * 8) * dstStride + k0 + tx] =
            __float2half_rn(ts[tx][ty + r * 8]);
}

// ---------------------------------------------------------------------------
// GEMM machinery: single fp16, BK=64, pitch-144 tiles, 2 stages.
// ---------------------------------------------------------------------------
#define TILE_BYTES   18432
#define STAGE_BYTES  (2 * TILE_BYTES)
#define GEMM_SMEM_BYTES (2 * STAGE_BYTES)

__device__ __forceinline__ void stage_copy(
    uint32_t sstage,
    const __half* __restrict__ A, int lda,
    const __half* __restrict__ B, int ldb, int k0, int tid)
{
    #pragma unroll
    for (int i = 0; i < 4; i++) {
        int idx = tid + i * 256;
        int row = idx >> 3;
        int seg = idx & 7;
        uint32_t so = row * 144 + seg * 16;
        CPA16(sstage +              so, A + (size_t)row * lda + k0 + seg * 8);
        CPA16(sstage + TILE_BYTES + so, B + (size_t)row * ldb + k0 + seg * 8);
    }
}

__device__ __forceinline__ void compute_stage(
    uint32_t sstage, uint32_t a_off, uint32_t b_off, float acc[4][4][4])
{
    #pragma unroll
    for (int ks = 0; ks < 4; ks++) {
        uint32_t ah[4][4], bh[2][4];
        #pragma unroll
        for (int mf = 0; mf < 4; mf++)
            LDSM4(ah[mf], sstage + a_off + mf * 2304 + ks * 32);
        #pragma unroll
        for (int np = 0; np < 2; np++)
            LDSM4(bh[np], sstage + TILE_BYTES + b_off + np * 2304 + ks * 32);
        #pragma unroll
        for (int mf = 0; mf < 4; mf++) {
            #pragma unroll
            for (int nf = 0; nf < 4; nf++) {
                MMA16816(acc[mf][nf], ah[mf],
                         bh[nf >> 1][(nf & 1) * 2], bh[nf >> 1][(nf & 1) * 2 + 1]);
            }
        }
    }
}

// ---------------------------------------------------------------------------
// proj_gemm: grid (64, 6), 256 threads, 2 CTAs/SM. Fused epilogues.
// ---------------------------------------------------------------------------
__global__ __launch_bounds__(256, 2) void proj_gemm(
    const float* __restrict__ bq, const float* __restrict__ bk,
    const float* __restrict__ bv, const float* __restrict__ bg)
{
    extern __shared__ char smraw[];
    __shared__ float sq2[128];
    uint32_t sbase = smem_u32(smraw);
    const int tid = threadIdx.x;
    const int m0 = blockIdx.x * 128;
    const int slab = blockIdx.y;
    const int nbase = slab * 128;

    if (tid < 128) sq2[tid] = 0.0f;

    const __half* A = g_Xh + (size_t)m0 * DD;
    const __half* B = g_Wt + (size_t)nbase * DD;

    const int warp = tid >> 5, lane = tid & 31;
    const int lr = lane & 7, gq = lane >> 3;
    const int wm = (warp & 1) * 64, wn = (warp >> 1) * 32;
    const uint32_t a_off = (wm + lr + (gq & 1) * 8) * 144 + (gq >> 1) * 16;
    const uint32_t b_off = (wn + lr + (gq >> 1) * 8) * 144 + (gq & 1) * 16;

    float acc[4][4][4] = {};

    stage_copy(sbase, A, DD, B, DD, 0, tid);
    CP_COMMIT();
    for (int kb = 0; kb < 16; kb++) {
        if (kb + 1 < 16) {
            stage_copy(sbase + ((kb + 1) & 1) * STAGE_BYTES,
                       A, DD, B, DD, (kb + 1) * 64, tid);
            CP_COMMIT();
            CP_WAIT1();
        } else {
            CP_WAIT0();
        }
        __syncthreads();
        compute_stage(sbase + (kb & 1) * STAGE_BYTES, a_off, b_off, acc);
        __syncthreads();
    }

    const int mrow = lane >> 2, ncol = (lane & 3) * 2;

    if (slab < 2) {
        const float* bias = (slab == 0) ? bq : bk;
        __half* dst = (slab == 0) ? g_Qh : g_Kh;
        float part[4][2] = {};
        #pragma unroll
        for (int mf = 0; mf < 4; mf++) {
            int lm = wm + mf * 16 + mrow;
            #pragma unroll
            for (int nf = 0; nf < 4; nf++) {
                int n = wn + nf * 8 + ncol;
                float b0 = bias[n], b1 = bias[n + 1];
                __half h00 = __float2half_rn(acc[mf][nf][0] + b0);
                __half h01 = __float2half_rn(acc[mf][nf][1] + b1);
                __half h10 = __float2half_rn(acc[mf][nf][2] + b0);
                __half h11 = __float2half_rn(acc[mf][nf][3] + b1);
                __half2 p0(h00, h01), p1(h10, h11);
                *(uint32_t*)&dst[(size_t)(m0 + lm) * DQKC + n] =
                    *reinterpret_cast<uint32_t*>(&p0);
                *(uint32_t*)&dst[(size_t)(m0 + lm + 8) * DQKC + n] =
                    *reinterpret_cast<uint32_t*>(&p1);
                float f00 = __half2float(h00), f01 = __half2float(h01);
                float f10 = __half2float(h10), f11 = __half2float(h11);
                part[mf][0] += f00 * f00 + f01 * f01;
                part[mf][1] += f10 * f10 + f11 * f11;
            }
        }
        #pragma unroll
        for (int mf = 0; mf < 4; mf++) {
            float s0 = part[mf][0], s1 = part[mf][1];
            s0 += __shfl_xor_sync(0xffffffffu, s0, 1);
            s0 += __shfl_xor_sync(0xffffffffu, s0, 2);
            s1 += __shfl_xor_sync(0xffffffffu, s1, 1);
            s1 += __shfl_xor_sync(0xffffffffu, s1, 2);
            if ((lane & 3) == 0) {
                int lm = wm + mf * 16 + mrow;
                atomicAdd(&sq2[lm], s0);
                atomicAdd(&sq2[lm + 8], s1);
            }
        }
        __syncthreads();
        if (tid < 128) {
            if (slab == 0) g_Q2[m0 + tid] = sq2[tid];
            else           g_K2[m0 + tid] = sq2[tid];
        }
    } else if (slab < 4) {
        __half* Vs = (__half*)smraw;
        const int VSP = 130;
        #pragma unroll
        for (int mf = 0; mf < 4; mf++) {
            int lm = wm + mf * 16 + mrow;
            #pragma unroll
            for (int nf = 0; nf < 4; nf++) {
                int n = wn + nf * 8 + ncol;
                float b0 = bv[((slab == 3) ? 128 : 0) + n];
                float b1 = bv[((slab == 3) ? 128 : 0) + n + 1];
                *(uint32_t*)&Vs[lm * VSP + n] =
                    pack2h(acc[mf][nf][0] + b0, acc[mf][nf][1] + b1);
                *(uint32_t*)&Vs[(lm + 8) * VSP + n] =
                    pack2h(acc[mf][nf][2] + b0, acc[mf][nf][3] + b1);
            }
        }
        __syncthreads();
        const int batch = m0 >> 11;
        const int mloc  = m0 & 2047;
        const int nbo   = (slab == 3) ? 128 : 0;
        #pragma unroll
        for (int i = 0; i < 8; i++) {
            int idx = tid + i * 256;
            int n = idx >> 4;
            int mseg = idx & 15;
            __half tmp[8];
            #pragma unroll
            for (int j = 0; j < 8; j++)
                tmp[j] = Vs[(mseg * 8 + j) * VSP + n];
            *(uint4*)&g_Vt[((size_t)batch * DVC + nbo + n) * SS + mloc + mseg * 8] =
                *(uint4*)tmp;
        }
    } else {
        const int nbo = (slab == 5) ? 128 : 0;
        #pragma unroll
        for (int mf = 0; mf < 4; mf++) {
            int m = m0 + wm + mf * 16 + mrow;
            #pragma unroll
            for (int nf = 0; nf < 4; nf++) {
                int n = wn + nf * 8 + ncol;
                float b0 = bg[nbo + n], b1 = bg[nbo + n + 1];
                *(uint32_t*)&g_Gh[(size_t)m * DVC + nbo + n] =
                    pack2h(acc[mf][nf][0] + b0, acc[mf][nf][1] + b1);
                *(uint32_t*)&g_Gh[(size_t)(m + 8) * DVC + nbo + n] =
                    pack2h(acc[mf][nf][2] + b0, acc[mf][nf][3] + b1);
            }
        }
    }
}

// ---------------------------------------------------------------------------
// attn: register-resident w (R13, unchanged).
// ---------------------------------------------------------------------------
#define QPITCH 272
#define KPITCH 272
#define VPITCH 144

#define KBUF_BYTES 17408
#define VBUF_BYTES 36864

#define OFF_QH  0
#define OFF_KH  17408
#define OFF_VH  69632
#define OFF_K2  180224
#define ATT_SMEM_BYTES 180992

#define WSCALE 1024.0f

__device__ __forceinline__ void attn_load_k(uint32_t sKh, int krow0c, int tid)
{
    #pragma unroll
    for (int i = 0; i < 4; i++) {
        int idx = tid + i * 256;
        int row = idx >> 4, seg = idx & 15;
        CPA16(sKh + row * KPITCH + seg * 16,
              g_Kh + (size_t)(krow0c + row) * DQKC + seg * 8);
    }
}

__device__ __forceinline__ void attn_load_v(uint32_t sVh, int b, int kb, int tid)
{
    #pragma unroll
    for (int i = 0; i < 8; i++) {
        int idx = tid + i * 256;
        int n = idx >> 3, seg = idx & 7;
        CPA16(sVh + n * VPITCH + seg * 16,
              g_Vt + ((size_t)b * DVC + n) * (size_t)SS + kb * 64 + seg * 8);
    }
}

__global__ __launch_bounds__(256) void attn_kernel()
{
    extern __shared__ char smc[];
    const uint32_t sb = smem_u32(smc);

    const int tid  = threadIdx.x;
    const int warp = tid >> 5, lane = tid & 31;
    const int lr = lane & 7, gq = lane >> 3;
    const int mrow = lane >> 2, ncol = (lane & 3) * 2;
    const int rg = warp & 3;
    const int ch = warp >> 2;

    const int b  = blockIdx.x >> 5;
    const int qt = blockIdx.x & 31;
    const int qrow0 = b * SS + qt * 64;
    const int krow0 = b * SS;

    #pragma unroll
    for (int i = 0; i < 4; i++) {
        int idx = tid + i * 256;
        int row = idx >> 4, seg = idx & 15;
        CPA16(sb + OFF_QH + row * QPITCH + seg * 16,
              g_Qh + (size_t)(qrow0 + row) * DQKC + seg * 8);
    }
    attn_load_k(sb + OFF_KH, krow0, tid);
    if (tid < 16) CPA16(sb + OFF_K2 + tid * 16, g_K2 + krow0 + tid * 4);
    CP_COMMIT();
    attn_load_v(sb + OFF_VH, b, 0, tid);
    CP_COMMIT();
    attn_load_k(sb + OFF_KH + KBUF_BYTES, krow0 + 64, tid);
    if (tid < 16) CPA16(sb + OFF_K2 + 256 + tid * 16, g_K2 + krow0 + 64 + tid * 4);
    CP_COMMIT();
    attn_load_v(sb + OFF_VH + VBUF_BYTES, b, 1, tid);
    CP_COMMIT();

    const int r0 = rg * 16 + mrow;
    const float q20 = g_Q2[qrow0 + r0];
    const float q21 = g_Q2[qrow0 + r0 + 8];
    float rs0 = 0.0f, rs1 = 0.0f;

    const uint32_t aQbase = sb + OFF_QH +
        (rg * 16 + lr + (gq & 1) * 8) * QPITCH + (gq >> 1) * 16;
    const uint32_t bK = (lr + (gq >> 1) * 8) * KPITCH + (gq & 1) * 16;
    const uint32_t bV = (ch * 128 + lr + (gq >> 1) * 8) * VPITCH + (gq & 1) * 16;

    float acc[16][4] = {};

    for (int kc = 0; kc < 32; kc++) {
        __syncthreads();

        if (kc + 2 < 32) {
            int j = (kc + 2) % 3;
            attn_load_k(sb + OFF_KH + j * KBUF_BYTES, krow0 + (kc + 2) * 64, tid);
            if (tid < 16) CPA16(sb + OFF_K2 + j * 256 + tid * 16,
                                g_K2 + krow0 + (kc + 2) * 64 + tid * 4);
        }
        CP_COMMIT();
        if (kc + 2 < 32) {
            int j = (kc + 2) % 3;
            attn_load_v(sb + OFF_VH + j * VBUF_BYTES, b, kc + 2, tid);
        }
        CP_COMMIT();

        CP_WAIT5();

        const uint32_t sKH = sb + OFF_KH + (kc % 3) * KBUF_BYTES + bK;
        float s[8][4];
        #pragma unroll
        for (int nt = 0; nt < 8; nt++)
            #pragma unroll
            for (int k = 0; k < 4; k++) s[nt][k] = 0.0f;
        #pragma unroll
        for (int ks = 0; ks < 8; ks++) {
            uint32_t ah[4], bh[4][4];
            LDSM4(ah, aQbase + ks * 32);
            #pragma unroll
            for (int np = 0; np < 4; np++)
                LDSM4(bh[np], sKH + np * 16 * KPITCH + ks * 32);
            #pragma unroll
            for (int nt = 0; nt < 8; nt++)
                MMA16816(s[nt], ah, bh[nt >> 1][(nt & 1) * 2],
                         bh[nt >> 1][(nt & 1) * 2 + 1]);
        }

        const float* k2c = (const float*)(smc + OFF_K2 + (kc % 3) * 256);
        uint32_t wf[4][4];
        #pragma unroll
        for (int nt = 0; nt < 8; nt++) {
            float k20 = k2c[nt * 8 + ncol], k21 = k2c[nt * 8 + ncol + 1];
            float d00 = fmaxf(fmaf(-2.0f, s[nt][0], q20 + k20), 1e-6f);
            float d01 = fmaxf(fmaf(-2.0f, s[nt][1], q20 + k21), 1e-6f);
            float d10 = fmaxf(fmaf(-2.0f, s[nt][2], q21 + k20), 1e-6f);
            float d11 = fmaxf(fmaf(-2.0f, s[nt][3], q21 + k21), 1e-6f);
            float w00 = __fdividef(WSCALE, d00);
            float w01 = __fdividef(WSCALE, d01);
            float w10 = __fdividef(WSCALE, d10);
            float w11 = __fdividef(WSCALE, d11);
            rs0 += w00 + w01;
            rs1 += w10 + w11;
            int ks = nt >> 1, ix = (nt & 1) * 2;
            wf[ks][ix]     = pack2h(w00, w01);
            wf[ks][ix + 1] = pack2h(w10, w11);
        }

        CP_WAIT4();

        const uint32_t sVH = sb + OFF_VH + (kc % 3) * VBUF_BYTES + bV;
        #pragma unroll
        for (int ks = 0; ks < 4; ks++) {
            uint32_t bvh[8][4];
            #pragma unroll
            for (int nn = 0; nn < 8; nn++)
                LDSM4(bvh[nn], sVH + nn * 16 * VPITCH + ks * 32);
            #pragma unroll
            for (int nf = 0; nf < 16; nf++)
                MMA16816(acc[nf], wf[ks], bvh[nf >> 1][(nf & 1) * 2],
                         bvh[nf >> 1][(nf & 1) * 2 + 1]);
        }
    }

    rs0 += __shfl_xor_sync(0xffffffffu, rs0, 1);
    rs0 += __shfl_xor_sync(0xffffffffu, rs0, 2);
    rs1 += __shfl_xor_sync(0xffffffffu, rs1, 1);
    rs1 += __shfl_xor_sync(0xffffffffu, rs1, 2);
    const float inv0 = 1.0f / rs0;
    const float inv1 = 1.0f / rs1;
    const size_t gm0 = (size_t)(qrow0 + r0) * DVC;
    const size_t gm1 = gm0 + 8 * DVC;
    #pragma unroll
    for (int nf = 0; nf < 16; nf++) {
        int n = ch * 128 + nf * 8 + ncol;
        float2 gA = __half22float2(*(const __half2*)&g_Gh[gm0 + n]);
        float2 gB = __half22float2(*(const __half2*)&g_Gh[gm1 + n]);
        *(uint32_t*)&g_Ph[gm0 + n] =
            pack2h(acc[nf][0] * inv0 * gA.x, acc[nf][1] * inv0 * gA.y);
        *(uint32_t*)&g_Ph[gm1 + n] =
            pack2h(acc[nf][2] * inv1 * gB.x, acc[nf][3] * inv1 * gB.y);
    }
}

// ---------------------------------------------------------------------------
// out_gemm: out = X + P @ Wp + bp   (BK=64, 4 k-blocks), 2 CTAs/SM  (R13)
// ---------------------------------------------------------------------------
__global__ __launch_bounds__(256, 2) void out_gemm(
    const float* __restrict__ X, const float* __restrict__ bp,
    float* __restrict__ outp)
{
    extern __shared__ char smraw[];
    uint32_t sbase = smem_u32(smraw);
    const int tid = threadIdx.x;
    const int m0 = blockIdx.x * 128;
    const int n0 = blockIdx.y * 128;

    const __half* A = g_Ph + (size_t)m0 * DVC;
    const __half* B = g_Wpt + (size_t)n0 * DVC;

    const int warp = tid >> 5, lane = tid & 31;
    const int lr = lane & 7, gq = lane >> 3;
    const int wm = (warp & 1) * 64, wn = (warp >> 1) * 32;
    const uint32_t a_off = (wm + lr + (gq & 1) * 8) * 144 + (gq >> 1) * 16;
    const uint32_t b_off = (wn + lr + (gq >> 1) * 8) * 144 + (gq & 1) * 16;

    float acc[4][4][4] = {};

    stage_copy(sbase, A, DVC, B, DVC, 0, tid);
    CP_COMMIT();
    for (int kb = 0; kb < 4; kb++) {
        if (kb + 1 < 4) {
            stage_copy(sbase + ((kb + 1) & 1) * STAGE_BYTES,
                       A, DVC, B, DVC, (kb + 1) * 64, tid);
            CP_COMMIT();
            CP_WAIT1();
        } else {
            CP_WAIT0();
        }
        __syncthreads();
        compute_stage(sbase + (kb & 1) * STAGE_BYTES, a_off, b_off, acc);
        __syncthreads();
    }

    const int mrow = lane >> 2, ncol = (lane & 3) * 2;
    #pragma unroll
    for (int mf = 0; mf < 4; mf++) {
        #pragma unroll
        for (int nf = 0; nf < 4; nf++) {
            int m = m0 + wm + mf * 16 + mrow;
            int n = n0 + wn + nf * 8 + ncol;
            float b0 = bp[n], b1 = bp[n + 1];
            float2 x0 = *(const float2*)&X[(size_t)m * DD + n];
            float2 x1 = *(const float2*)&X[(size_t)(m + 8) * DD + n];
            *(float2*)&outp[(size_t)m * DD + n] =
                make_float2(acc[mf][nf][0] + b0 + x0.x, acc[mf][nf][1] + b1 + x0.y);
            *(float2*)&outp[(size_t)(m + 8) * DD + n] =
                make_float2(acc[mf][nf][2] + b0 + x1.x, acc[mf][nf][3] + b1 + x1.y);
        }
    }
}

// ---------------------------------------------------------------------------
extern "C" void kernel_launch(void* const* d_in, const int* in_sizes, int n_in,
                              void* d_out, int out_size)
{
    const float* X  = (const float*)d_in[0];
    const float* Wq = (const float*)d_in[1];
    const float* bq = (const float*)d_in[2];
    const float* Wk = (const float*)d_in[3];
    const float* bk = (const float*)d_in[4];
    const float* Wv = (const float*)d_in[5];
    const float* bv = (const float*)d_in[6];
    const float* Wg = (const float*)d_in[7];
    const float* bg = (const float*)d_in[8];
    const float* Wp = (const float*)d_in[9];
    const float* bp = (const float*)d_in[10];
    float* out = (float*)d_out;

    cudaFuncSetAttribute(proj_gemm, cudaFuncAttributeMaxDynamicSharedMemorySize, GEMM_SMEM_BYTES);
    cudaFuncSetAttribute(out_gemm,  cudaFuncAttributeMaxDynamicSharedMemorySize, GEMM_SMEM_BYTES);
    cudaFuncSetAttribute(attn_kernel, cudaFuncAttributeMaxDynamicSharedMemorySize, ATT_SMEM_BYTES);

    prep_kernel<<<XB + WTILES, 256>>>(X, Wq, Wk, Wv, Wg, Wp);
    proj_gemm<<<dim3(64, 6), 256, GEMM_SMEM_BYTES>>>(bq, bk, bv, bg);
    attn_kernel<<<128, 256, ATT_SMEM_BYTES>>>();
    out_gemm<<<dim3(64, 8), 256, GEMM_SMEM_BYTES>>>(X, bp, out);
}

// round 17
// speedup vs baseline: 1.1354x; 1.0828x over previous
#include <cuda_runtime.h>
#include <cuda_fp16.h>
#include <cstdint>

#define BB   4
#define SS   2048
#define DD   1024
#define DQKC 128
#define DVC  256
#define MM   (BB * SS)   // 8192
#define NPROJ 768

// ---------------------------------------------------------------------------
// Device scratch (all fp16 operands)
// ---------------------------------------------------------------------------
__device__ __align__(256) __half g_Xh[MM * DD];
__device__ __align__(256) __half g_Wt[NPROJ * DD];      // [n][k]
__device__ __align__(256) __half g_Wpt[DD * DVC];       // [n][k]
__device__ __align__(256) __half g_Qh[MM * DQKC];
__device__ __align__(256) __half g_Kh[MM * DQKC];
__device__ __align__(256) __half g_Vt[BB * DVC * SS];   // [b][n][s]
__device__ __align__(256) __half g_Gh[MM * DVC];
__device__ __align__(256) __half g_Ph[MM * DVC];        // (AV*G)
__device__ __align__(256) float g_Q2[MM];
__device__ __align__(256) float g_K2[MM];

// ---------------------------------------------------------------------------
// PTX helpers
// ---------------------------------------------------------------------------
__device__ __forceinline__ uint32_t smem_u32(const void* p) {
    uint32_t a;
    asm("{ .reg .u64 t; cvta.to.shared.u64 t, %1; cvt.u32.u64 %0, t; }"
        : "=r"(a) : "l"(p));
    return a;
}

#define LDSM4(r, addr) \
    asm volatile("ldmatrix.sync.aligned.m8n8.x4.shared.b16 {%0,%1,%2,%3}, [%4];" \
        : "=r"((r)[0]), "=r"((r)[1]), "=r"((r)[2]), "=r"((r)[3]) : "r"(addr))

#define MMA16816(c, a, b0, b1) \
    asm volatile("mma.sync.aligned.m16n8k16.row.col.f32.f16.f16.f32 " \
        "{%0,%1,%2,%3}, {%4,%5,%6,%7}, {%8,%9}, {%0,%1,%2,%3};" \
        : "+f"((c)[0]), "+f"((c)[1]), "+f"((c)[2]), "+f"((c)[3]) \
        : "r"((a)[0]), "r"((a)[1]), "r"((a)[2]), "r"((a)[3]), "r"(b0), "r"(b1))

#define CPA16(s, g) \
    asm volatile("cp.async.ca.shared.global [%0], [%1], 16;" :: "r"(s), "l"(g) : "memory")
#define CP_COMMIT() asm volatile("cp.async.commit_group;" ::: "memory")
#define CP_WAIT0()  asm volatile("cp.async.wait_group 0;" ::: "memory")
#define CP_WAIT1()  asm volatile("cp.async.wait_group 1;" ::: "memory")
#define CP_WAIT4()  asm volatile("cp.async.wait_group 4;" ::: "memory")
#define CP_WAIT5()  asm volatile("cp.async.wait_group 5;" ::: "memory")

#define STS128F(a, p) \
    asm volatile("st.shared.v4.b32 [%0], {%1, %2, %3, %4};" \
        :: "r"(a), "r"(__float_as_uint((p)[0])), "r"(__float_as_uint((p)[1])), \
           "r"(__float_as_uint((p)[2])), "r"(__float_as_uint((p)[3])) : "memory")

__device__ __forceinline__ uint32_t pack2h(float a, float b) {
    __half2 hp(__float2half_rn(a), __float2half_rn(b));
    return *reinterpret_cast<uint32_t*>(&hp);
}

// ---------------------------------------------------------------------------
// Prep: blocks [0, XB) convert X; blocks [XB, XB+1024) transpose weights via
// 32x32 SMEM tiles (coalesced fp32 reads, coalesced fp16 writes).
// ---------------------------------------------------------------------------
#define XB (MM * DD / 1024)     // 8192
#define WTILES 1024

__global__ __launch_bounds__(256) void prep_kernel(
    const float* __restrict__ X,
    const float* __restrict__ Wq, const float* __restrict__ Wk,
    const float* __restrict__ Wv, const float* __restrict__ Wg,
    const float* __restrict__ Wp)
{
    const int tid = threadIdx.x;
    if (blockIdx.x < XB) {
        int i = (blockIdx.x * 256 + tid) * 4;
        float4 v = *(const float4*)&X[i];
        *(uint2*)&g_Xh[i] = make_uint2(pack2h(v.x, v.y), pack2h(v.z, v.w));
        return;
    }
    __shared__ float ts[32][33];
    int t = blockIdx.x - XB;
    const float* src; __half* dst;
    int srcN, dstStride, nbase, tilesN;
    if (t < 128)      { src = Wq; srcN = 128;  dst = g_Wt;  dstStride = DD;  nbase = 0;   tilesN = 4;  }
    else if (t < 256) { src = Wk; srcN = 128;  dst = g_Wt;  dstStride = DD;  nbase = 128; tilesN = 4;  t -= 128; }
    else if (t < 512) { src = Wv; srcN = 256;  dst = g_Wt;  dstStride = DD;  nbase = 256; tilesN = 8;  t -= 256; }
    else if (t < 768) { src = Wg; srcN = 256;  dst = g_Wt;  dstStride = DD;  nbase = 512; tilesN = 8;  t -= 512; }
    else              { src = Wp; srcN = 1024; dst = g_Wpt; dstStride = DVC; nbase = 0;   tilesN = 32; t -= 768; }
    const int k0 = (t / tilesN) * 32;
    const int n0 = (t % tilesN) * 32;
    const int tx = tid & 31, ty = tid >> 5;
    #pragma unroll
    for (int r = 0; r < 4; r++)
        ts[ty + r * 8][tx] = src[(size_t)(k0 + ty + r * 8) * srcN + n0 + tx];
    __syncthreads();
    #pragma unroll
    for (int r = 0; r < 4; r++)
        dst[(size_t)(nbase + n0 + ty + r * 8) * dstStride + k0 + tx] =
            __float2half_rn(ts[tx][ty + r * 8]);
}

// ---------------------------------------------------------------------------
// GEMM machinery: single fp16, BK=64, pitch-144 tiles, 2 stages.
// ---------------------------------------------------------------------------
#define TILE_BYTES   18432
#define STAGE_BYTES  (2 * TILE_BYTES)
#define GEMM_SMEM_BYTES (2 * STAGE_BYTES)

__device__ __forceinline__ void stage_copy(
    uint32_t sstage,
    const __half* __restrict__ A, int lda,
    const __half* __restrict__ B, int ldb, int k0, int tid)
{
    #pragma unroll
    for (int i = 0; i < 4; i++) {
        int idx = tid + i * 256;
        int row = idx >> 3;
        int seg = idx & 7;
        uint32_t so = row * 144 + seg * 16;
        CPA16(sstage +              so, A + (size_t)row * lda + k0 + seg * 8);
        CPA16(sstage + TILE_BYTES + so, B + (size_t)row * ldb + k0 + seg * 8);
    }
}

__device__ __forceinline__ void compute_stage(
    uint32_t sstage, uint32_t a_off, uint32_t b_off, float acc[4][4][4])
{
    #pragma unroll
    for (int ks = 0; ks < 4; ks++) {
        uint32_t ah[4][4], bh[2][4];
        #pragma unroll
        for (int mf = 0; mf < 4; mf++)
            LDSM4(ah[mf], sstage + a_off + mf * 2304 + ks * 32);
        #pragma unroll
        for (int np = 0; np < 2; np++)
            LDSM4(bh[np], sstage + TILE_BYTES + b_off + np * 2304 + ks * 32);
        #pragma unroll
        for (int mf = 0; mf < 4; mf++) {
            #pragma unroll
            for (int nf = 0; nf < 4; nf++) {
                MMA16816(acc[mf][nf], ah[mf],
                         bh[nf >> 1][(nf & 1) * 2], bh[nf >> 1][(nf & 1) * 2 + 1]);
            }
        }
    }
}

// ---------------------------------------------------------------------------
// proj_gemm: grid (64, 6), 256 threads, 2 CTAs/SM. Fused epilogues.
// ---------------------------------------------------------------------------
__global__ __launch_bounds__(256, 2) void proj_gemm(
    const float* __restrict__ bq, const float* __restrict__ bk,
    const float* __restrict__ bv, const float* __restrict__ bg)
{
    extern __shared__ char smraw[];
    __shared__ float sq2[128];
    uint32_t sbase = smem_u32(smraw);
    const int tid = threadIdx.x;
    const int m0 = blockIdx.x * 128;
    const int slab = blockIdx.y;
    const int nbase = slab * 128;

    if (tid < 128) sq2[tid] = 0.0f;

    const __half* A = g_Xh + (size_t)m0 * DD;
    const __half* B = g_Wt + (size_t)nbase * DD;

    const int warp = tid >> 5, lane = tid & 31;
    const int lr = lane & 7, gq = lane >> 3;
    const int wm = (warp & 1) * 64, wn = (warp >> 1) * 32;
    const uint32_t a_off = (wm + lr + (gq & 1) * 8) * 144 + (gq >> 1) * 16;
    const uint32_t b_off = (wn + lr + (gq >> 1) * 8) * 144 + (gq & 1) * 16;

    float acc[4][4][4] = {};

    stage_copy(sbase, A, DD, B, DD, 0, tid);
    CP_COMMIT();
    for (int kb = 0; kb < 16; kb++) {
        if (kb + 1 < 16) {
            stage_copy(sbase + ((kb + 1) & 1) * STAGE_BYTES,
                       A, DD, B, DD, (kb + 1) * 64, tid);
            CP_COMMIT();
            CP_WAIT1();
        } else {
            CP_WAIT0();
        }
        __syncthreads();
        compute_stage(sbase + (kb & 1) * STAGE_BYTES, a_off, b_off, acc);
        __syncthreads();
    }

    const int mrow = lane >> 2, ncol = (lane & 3) * 2;

    if (slab < 2) {
        const float* bias = (slab == 0) ? bq : bk;
        __half* dst = (slab == 0) ? g_Qh : g_Kh;
        float part[4][2] = {};
        #pragma unroll
        for (int mf = 0; mf < 4; mf++) {
            int lm = wm + mf * 16 + mrow;
            #pragma unroll
            for (int nf = 0; nf < 4; nf++) {
                int n = wn + nf * 8 + ncol;
                float b0 = bias[n], b1 = bias[n + 1];
                __half h00 = __float2half_rn(acc[mf][nf][0] + b0);
                __half h01 = __float2half_rn(acc[mf][nf][1] + b1);
                __half h10 = __float2half_rn(acc[mf][nf][2] + b0);
                __half h11 = __float2half_rn(acc[mf][nf][3] + b1);
                __half2 p0(h00, h01), p1(h10, h11);
                *(uint32_t*)&dst[(size_t)(m0 + lm) * DQKC + n] =
                    *reinterpret_cast<uint32_t*>(&p0);
                *(uint32_t*)&dst[(size_t)(m0 + lm + 8) * DQKC + n] =
                    *reinterpret_cast<uint32_t*>(&p1);
                float f00 = __half2float(h00), f01 = __half2float(h01);
                float f10 = __half2float(h10), f11 = __half2float(h11);
                part[mf][0] += f00 * f00 + f01 * f01;
                part[mf][1] += f10 * f10 + f11 * f11;
            }
        }
        #pragma unroll
        for (int mf = 0; mf < 4; mf++) {
            float s0 = part[mf][0], s1 = part[mf][1];
            s0 += __shfl_xor_sync(0xffffffffu, s0, 1);
            s0 += __shfl_xor_sync(0xffffffffu, s0, 2);
            s1 += __shfl_xor_sync(0xffffffffu, s1, 1);
            s1 += __shfl_xor_sync(0xffffffffu, s1, 2);
            if ((lane & 3) == 0) {
                int lm = wm + mf * 16 + mrow;
                atomicAdd(&sq2[lm], s0);
                atomicAdd(&sq2[lm + 8], s1);
            }
        }
        __syncthreads();
        if (tid < 128) {
            if (slab == 0) g_Q2[m0 + tid] = sq2[tid];
            else           g_K2[m0 + tid] = sq2[tid];
        }
    } else if (slab < 4) {
        __half* Vs = (__half*)smraw;
        const int VSP = 130;
        #pragma unroll
        for (int mf = 0; mf < 4; mf++) {
            int lm = wm + mf * 16 + mrow;
            #pragma unroll
            for (int nf = 0; nf < 4; nf++) {
                int n = wn + nf * 8 + ncol;
                float b0 = bv[((slab == 3) ? 128 : 0) + n];
                float b1 = bv[((slab == 3) ? 128 : 0) + n + 1];
                *(uint32_t*)&Vs[lm * VSP + n] =
                    pack2h(acc[mf][nf][0] + b0, acc[mf][nf][1] + b1);
                *(uint32_t*)&Vs[(lm + 8) * VSP + n] =
                    pack2h(acc[mf][nf][2] + b0, acc[mf][nf][3] + b1);
            }
        }
        __syncthreads();
        const int batch = m0 >> 11;
        const int mloc  = m0 & 2047;
        const int nbo   = (slab == 3) ? 128 : 0;
        #pragma unroll
        for (int i = 0; i < 8; i++) {
            int idx = tid + i * 256;
            int n = idx >> 4;
            int mseg = idx & 15;
            __half tmp[8];
            #pragma unroll
            for (int j = 0; j < 8; j++)
                tmp[j] = Vs[(mseg * 8 + j) * VSP + n];
            *(uint4*)&g_Vt[((size_t)batch * DVC + nbo + n) * SS + mloc + mseg * 8] =
                *(uint4*)tmp;
        }
    } else {
        const int nbo = (slab == 5) ? 128 : 0;
        #pragma unroll
        for (int mf = 0; mf < 4; mf++) {
            int m = m0 + wm + mf * 16 + mrow;
            #pragma unroll
            for (int nf = 0; nf < 4; nf++) {
                int n = wn + nf * 8 + ncol;
                float b0 = bg[nbo + n], b1 = bg[nbo + n + 1];
                *(uint32_t*)&g_Gh[(size_t)m * DVC + nbo + n] =
                    pack2h(acc[mf][nf][0] + b0, acc[mf][nf][1] + b1);
                *(uint32_t*)&g_Gh[(size_t)(m + 8) * DVC + nbo + n] =
                    pack2h(acc[mf][nf][2] + b0, acc[mf][nf][3] + b1);
            }
        }
    }
}

// ---------------------------------------------------------------------------
// attn: de-duplicated phase A. Warp = (rg: 16 q-rows) x (kh: 32-key half).
// Phase A: S[16 x 32] per warp. Phase B: partial acc over 32 keys x 256 cols.
// End: one SMEM accumulator exchange between partner warps (rg,0)<->(rg,1).
// ---------------------------------------------------------------------------
#define QPITCH 272
#define KPITCH 272
#define VPITCH 144

#define KBUF_BYTES 17408
#define VBUF_BYTES 36864

#define OFF_QH  0
#define OFF_KH  17408
#define OFF_VH  69632
#define OFF_K2  180224
#define ATT_SMEM_BYTES 180992

#define WSCALE 1024.0f

__device__ __forceinline__ void attn_load_k(uint32_t sKh, int krow0c, int tid)
{
    #pragma unroll
    for (int i = 0; i < 4; i++) {
        int idx = tid + i * 256;
        int row = idx >> 4, seg = idx & 15;
        CPA16(sKh + row * KPITCH + seg * 16,
              g_Kh + (size_t)(krow0c + row) * DQKC + seg * 8);
    }
}

__device__ __forceinline__ void attn_load_v(uint32_t sVh, int b, int kb, int tid)
{
    #pragma unroll
    for (int i = 0; i < 8; i++) {
        int idx = tid + i * 256;
        int n = idx >> 3, seg = idx & 7;
        CPA16(sVh + n * VPITCH + seg * 16,
              g_Vt + ((size_t)b * DVC + n) * (size_t)SS + kb * 64 + seg * 8);
    }
}

__global__ __launch_bounds__(256) void attn_kernel()
{
    extern __shared__ char smc[];
    const uint32_t sb = smem_u32(smc);

    const int tid  = threadIdx.x;
    const int warp = tid >> 5, lane = tid & 31;
    const int lr = lane & 7, gq = lane >> 3;
    const int mrow = lane >> 2, ncol = (lane & 3) * 2;
    const int rg = warp >> 1;       // row group: 16 q-rows
    const int kh = warp & 1;        // key half: 32 keys

    const int b  = blockIdx.x >> 5;
    const int qt = blockIdx.x & 31;
    const int qrow0 = b * SS + qt * 64;
    const int krow0 = b * SS;

    #pragma unroll
    for (int i = 0; i < 4; i++) {
        int idx = tid + i * 256;
        int row = idx >> 4, seg = idx & 15;
        CPA16(sb + OFF_QH + row * QPITCH + seg * 16,
              g_Qh + (size_t)(qrow0 + row) * DQKC + seg * 8);
    }
    attn_load_k(sb + OFF_KH, krow0, tid);
    if (tid < 16) CPA16(sb + OFF_K2 + tid * 16, g_K2 + krow0 + tid * 4);
    CP_COMMIT();
    attn_load_v(sb + OFF_VH, b, 0, tid);
    CP_COMMIT();
    attn_load_k(sb + OFF_KH + KBUF_BYTES, krow0 + 64, tid);
    if (tid < 16) CPA16(sb + OFF_K2 + 256 + tid * 16, g_K2 + krow0 + 64 + tid * 4);
    CP_COMMIT();
    attn_load_v(sb + OFF_VH + VBUF_BYTES, b, 1, tid);
    CP_COMMIT();

    const int r0 = rg * 16 + mrow;
    const float q20 = g_Q2[qrow0 + r0];
    const float q21 = g_Q2[qrow0 + r0 + 8];
    float rs0 = 0.0f, rs1 = 0.0f;   // partial (this warp's 32 keys)

    const uint32_t aQbase = sb + OFF_QH +
        (rg * 16 + lr + (gq & 1) * 8) * QPITCH + (gq >> 1) * 16;
    const uint32_t bKb = (kh * 32 + lr + (gq >> 1) * 8) * KPITCH + (gq & 1) * 16;
    const uint32_t bVb = (lr + (gq >> 1) * 8) * VPITCH + kh * 64 + (gq & 1) * 16;

    float acc[32][4] = {};          // 16 q-rows x 256 cols (partial over 32 keys)

    for (int kc = 0; kc < 32; kc++) {
        __syncthreads();

        if (kc + 2 < 32) {
            int j = (kc + 2) % 3;
            attn_load_k(sb + OFF_KH + j * KBUF_BYTES, krow0 + (kc + 2) * 64, tid);
            if (tid < 16) CPA16(sb + OFF_K2 + j * 256 + tid * 16,
                                g_K2 + krow0 + (kc + 2) * 64 + tid * 4);
        }
        CP_COMMIT();
        if (kc + 2 < 32) {
            int j = (kc + 2) % 3;
            attn_load_v(sb + OFF_VH + j * VBUF_BYTES, b, kc + 2, tid);
        }
        CP_COMMIT();

        CP_WAIT5();   // K(kc) (+Q on kc==0) ready

        // ---- Phase A: S[16 x 32] = Q(rows rg) @ K(keys kh*32..)^T, K=128 ----
        const uint32_t sKH = sb + OFF_KH + (kc % 3) * KBUF_BYTES + bKb;
        float s[4][4];
        #pragma unroll
        for (int nt = 0; nt < 4; nt++)
            #pragma unroll
            for (int k = 0; k < 4; k++) s[nt][k] = 0.0f;
        #pragma unroll
        for (int ks = 0; ks < 8; ks++) {
            uint32_t ah[4], bh[2][4];
            LDSM4(ah, aQbase + ks * 32);
            LDSM4(bh[0], sKH + ks * 32);
            LDSM4(bh[1], sKH + 16 * KPITCH + ks * 32);
            MMA16816(s[0], ah, bh[0][0], bh[0][1]);
            MMA16816(s[1], ah, bh[0][2], bh[0][3]);
            MMA16816(s[2], ah, bh[1][0], bh[1][1]);
            MMA16816(s[3], ah, bh[1][2], bh[1][3]);
        }

        // ---- w in registers: A-fragments for phase B (2 k16 tiles) ----
        const float* k2c = (const float*)(smc + OFF_K2 + (kc % 3) * 256);
        uint32_t wf[2][4];
        #pragma unroll
        for (int nt = 0; nt < 4; nt++) {
            int kidx = kh * 32 + nt * 8 + ncol;
            float k20 = k2c[kidx], k21 = k2c[kidx + 1];
            float d00 = fmaxf(fmaf(-2.0f, s[nt][0], q20 + k20), 1e-6f);
            float d01 = fmaxf(fmaf(-2.0f, s[nt][1], q20 + k21), 1e-6f);
            float d10 = fmaxf(fmaf(-2.0f, s[nt][2], q21 + k20), 1e-6f);
            float d11 = fmaxf(fmaf(-2.0f, s[nt][3], q21 + k21), 1e-6f);
            float w00 = __fdividef(WSCALE, d00);
            float w01 = __fdividef(WSCALE, d01);
            float w10 = __fdividef(WSCALE, d10);
            float w11 = __fdividef(WSCALE, d11);
            rs0 += w00 + w01;
            rs1 += w10 + w11;
            int ksl = nt >> 1, ix = (nt & 1) * 2;
            wf[ksl][ix]     = pack2h(w00, w01);
            wf[ksl][ix + 1] = pack2h(w10, w11);
        }

        CP_WAIT4();   // V(kc) ready

        // ---- Phase B: acc += w @ V  (16 rows x 256 cols, 32 keys) ----
        const uint32_t sVH = sb + OFF_VH + (kc % 3) * VBUF_BYTES + bVb;
        #pragma unroll
        for (int ksl = 0; ksl < 2; ksl++) {
            #pragma unroll
            for (int nn = 0; nn < 16; nn++) {
                uint32_t bvh[4];
                LDSM4(bvh, sVH + nn * 16 * VPITCH + ksl * 32);
                MMA16816(acc[nn * 2],     wf[ksl], bvh[0], bvh[1]);
                MMA16816(acc[nn * 2 + 1], wf[ksl], bvh[2], bvh[3]);
            }
        }
    }

    // ---- Cross-warp accumulator exchange (once) ----
    // Warp (rg,kh) keeps cols [kh*128, kh*128+128) (nf kh*16..), gives the rest.
    __syncthreads();   // all phase-B reads of V buffers done; reuse as exchange
    const uint32_t exb = sb + OFF_VH;
    const uint32_t myw = exb + warp * 8192 + lane * 16;
    if (kh == 0) {
        #pragma unroll
        for (int j = 0; j < 16; j++) STS128F(myw + j * 512, acc[16 + j]);
    } else {
        #pragma unroll
        for (int j = 0; j < 16; j++) STS128F(myw + j * 512, acc[j]);
    }
    // row-sum partial exchange (quad-reduce first; all lanes hold value)
    rs0 += __shfl_xor_sync(0xffffffffu, rs0, 1);
    rs0 += __shfl_xor_sync(0xffffffffu, rs0, 2);
    rs1 += __shfl_xor_sync(0xffffffffu, rs1, 1);
    rs1 += __shfl_xor_sync(0xffffffffu, rs1, 2);
    float2* rsx = (float2*)(smc + (OFF_VH + 65536));
    rsx[warp * 32 + lane] = make_float2(rs0, rs1);
    __syncthreads();
    const int pw = warp ^ 1;
    const uint32_t pwb = exb + pw * 8192 + lane * 16;
    if (kh == 0) {
        #pragma unroll
        for (int j = 0; j < 16; j++) {
            float4 v = *(const float4*)(smc + (pwb - sb) + j * 512);
            acc[j][0] += v.x; acc[j][1] += v.y; acc[j][2] += v.z; acc[j][3] += v.w;
        }
    } else {
        #pragma unroll
        for (int j = 0; j < 16; j++) {
            float4 v = *(const float4*)(smc + (pwb - sb) + j * 512);
            acc[16 + j][0] += v.x; acc[16 + j][1] += v.y;
            acc[16 + j][2] += v.z; acc[16 + j][3] += v.w;
        }
    }
    float2 prs = rsx[pw * 32 + lane];
    const float inv0 = 1.0f / (rs0 + prs.x);
    const float inv1 = 1.0f / (rs1 + prs.y);

    // ---- Epilogue: normalize, gate with fp16 G, pack P ----
    const size_t gm0 = (size_t)(qrow0 + r0) * DVC;
    const size_t gm1 = gm0 + 8 * DVC;
    const int nfb = kh * 16;
    #pragma unroll
    for (int j = 0; j < 16; j++) {
        int n = kh * 128 + j * 8 + ncol;
        float2 gA = __half22float2(*(const __half2*)&g_Gh[gm0 + n]);
        float2 gB = __half22float2(*(const __half2*)&g_Gh[gm1 + n]);
        float a0, a1, a2, a3;
        if (kh == 0) { a0 = acc[j][0]; a1 = acc[j][1]; a2 = acc[j][2]; a3 = acc[j][3]; }
        else         { a0 = acc[16+j][0]; a1 = acc[16+j][1]; a2 = acc[16+j][2]; a3 = acc[16+j][3]; }
        *(uint32_t*)&g_Ph[gm0 + n] = pack2h(a0 * inv0 * gA.x, a1 * inv0 * gA.y);
        *(uint32_t*)&g_Ph[gm1 + n] = pack2h(a2 * inv1 * gB.x, a3 * inv1 * gB.y);
    }
}

// ---------------------------------------------------------------------------
// out_gemm: out = X + P @ Wp + bp   (BK=64, 4 k-blocks), 2 CTAs/SM  (R13)
// ---------------------------------------------------------------------------
__global__ __launch_bounds__(256, 2) void out_gemm(
    const float* __restrict__ X, const float* __restrict__ bp,
    float* __restrict__ outp)
{
    extern __shared__ char smraw[];
    uint32_t sbase = smem_u32(smraw);
    const int tid = threadIdx.x;
    const int m0 = blockIdx.x * 128;
    const int n0 = blockIdx.y * 128;

    const __half* A = g_Ph + (size_t)m0 * DVC;
    const __half* B = g_Wpt + (size_t)n0 * DVC;

    const int warp = tid >> 5, lane = tid & 31;
    const int lr = lane & 7, gq = lane >> 3;
    const int wm = (warp & 1) * 64, wn = (warp >> 1) * 32;
    const uint32_t a_off = (wm + lr + (gq & 1) * 8) * 144 + (gq >> 1) * 16;
    const uint32_t b_off = (wn + lr + (gq >> 1) * 8) * 144 + (gq & 1) * 16;

    float acc[4][4][4] = {};

    stage_copy(sbase, A, DVC, B, DVC, 0, tid);
    CP_COMMIT();
    for (int kb = 0; kb < 4; kb++) {
        if (kb + 1 < 4) {
            stage_copy(sbase + ((kb + 1) & 1) * STAGE_BYTES,
                       A, DVC, B, DVC, (kb + 1) * 64, tid);
            CP_COMMIT();
            CP_WAIT1();
        } else {
            CP_WAIT0();
        }
        __syncthreads();
        compute_stage(sbase + (kb & 1) * STAGE_BYTES, a_off, b_off, acc);
        __syncthreads();
    }

    const int mrow = lane >> 2, ncol = (lane & 3) * 2;
    #pragma unroll
    for (int mf = 0; mf < 4; mf++) {
        #pragma unroll
        for (int nf = 0; nf < 4; nf++) {
            int m = m0 + wm + mf * 16 + mrow;
            int n = n0 + wn + nf * 8 + ncol;
            float b0 = bp[n], b1 = bp[n + 1];
            float2 x0 = *(const float2*)&X[(size_t)m * DD + n];
            float2 x1 = *(const float2*)&X[(size_t)(m + 8) * DD + n];
            *(float2*)&outp[(size_t)m * DD + n] =
                make_float2(acc[mf][nf][0] + b0 + x0.x, acc[mf][nf][1] + b1 + x0.y);
            *(float2*)&outp[(size_t)(m + 8) * DD + n] =
                make_float2(acc[mf][nf][2] + b0 + x1.x, acc[mf][nf][3] + b1 + x1.y);
        }
    }
}

// ---------------------------------------------------------------------------
extern "C" void kernel_launch(void* const* d_in, const int* in_sizes, int n_in,
                              void* d_out, int out_size)
{
    const float* X  = (const float*)d_in[0];
    const float* Wq = (const float*)d_in[1];
    const float* bq = (const float*)d_in[2];
    const float* Wk = (const float*)d_in[3];
    const float* bk = (const float*)d_in[4];
    const float* Wv = (const float*)d_in[5];
    const float* bv = (const float*)d_in[6];
    const float* Wg = (const float*)d_in[7];
    const float* bg = (const float*)d_in[8];
    const float* Wp = (const float*)d_in[9];
    const float* bp = (const float*)d_in[10];
    float* out = (float*)d_out;

    cudaFuncSetAttribute(proj_gemm, cudaFuncAttributeMaxDynamicSharedMemorySize, GEMM_SMEM_BYTES);
    cudaFuncSetAttribute(out_gemm,  cudaFuncAttributeMaxDynamicSharedMemorySize, GEMM_SMEM_BYTES);
    cudaFuncSetAttribute(attn_kernel, cudaFuncAttributeMaxDynamicSharedMemorySize, ATT_SMEM_BYTES);

    prep_kernel<<<XB + WTILES, 256>>>(X, Wq, Wk, Wv, Wg, Wp);
    proj_gemm<<<dim3(64, 6), 256, GEMM_SMEM_BYTES>>>(bq, bk, bv, bg);
    attn_kernel<<<128, 256, ATT_SMEM_BYTES>>>();
    out_gemm<<<dim3(64, 8), 256, GEMM_SMEM_BYTES>>>(X, bp, out);
}